// round 1
// baseline (speedup 1.0000x reference)
#include <cuda_runtime.h>
#include <math.h>

#define NROW 4096
#define KDIM 4096
#define NCLS 20
#define MT   64          // rows per CTA in GEMM
#define KB   32          // K-chunk staged in smem
#define KSPLIT 4
#define KCHUNK (KDIM / KSPLIT)   // 1024
#define PCOLS 96         // partial buffer stride: 0..61 roi-cols(cls|r1|r2), 64..83 det

// ---------------- scratch (device globals; no allocation allowed) ----------------
__device__ float g_part[KSPLIT][NROW][PCOLS];      // ~6.3 MB split-K partials
__device__ float g_cls_score[NROW][NCLS];
__device__ float g_cls_prob [NROW][NCLS];
__device__ float g_prob1[NROW][NCLS + 1];
__device__ float g_prob2[NROW][NCLS + 1];
__device__ float g_det  [NROW][NCLS];
__device__ float g_dcs  [NCLS];
__device__ float g_qbox [2][NCLS][4];

// =====================================================================
// K1: fused split-K GEMM.
//   cols 0..19  : roi @ W_cls
//   cols 20..40 : roi @ W_r1
//   cols 41..61 : roi @ W_r2
//   cols 64..83 : (frame - ctx) @ W_det        (b_det cancels)
// A tiles stored transposed in smem with an XOR swizzle on the float4
// column group: element (k, r) lives at word  k*64 + (((r>>2)^(k>>2))<<2) + (r&3).
// This makes both the 4-scalar transpose STS (32 distinct banks across the
// warp) and the float4 compute LDS (2 broadcast addresses/warp) conflict-free.
// =====================================================================
__global__ void __launch_bounds__(256)
k1_gemm(const float* __restrict__ roi, const float* __restrict__ ctx,
        const float* __restrict__ frm,
        const float* __restrict__ Wc,  const float* __restrict__ Wd,
        const float* __restrict__ W1,  const float* __restrict__ W2)
{
    __shared__ float s_roi[KB * 64];
    __shared__ float s_dif[KB * 64];
    __shared__ float s_w  [KB * 64];   // 64 roi-side weight cols (62 real + 2 zero)
    __shared__ float s_wd [KB * 32];   // det weight cols, zero-padded 20->32

    const int tid = threadIdx.x;
    const int tx  = tid & 15;          // col-thread
    const int ty  = tid >> 4;          // row-thread
    const int m0  = blockIdx.x * MT;
    const int k0  = blockIdx.y * KCHUNK;

    float acc[4][4];
    float accd[4][2];
#pragma unroll
    for (int i = 0; i < 4; ++i) {
#pragma unroll
        for (int j = 0; j < 4; ++j) acc[i][j] = 0.f;
        accd[i][0] = 0.f; accd[i][1] = 0.f;
    }

    for (int kc = 0; kc < KCHUNK / KB; ++kc) {
        const int kb = k0 + kc * KB;

        // ---- stage A streams (512 float4 per stream, 2 per thread) ----
#pragma unroll
        for (int s = 0; s < 2; ++s) {
            const int flat = tid + s * 256;
            const int r  = flat >> 3;       // 0..63
            const int kq = flat & 7;        // float4 index within chunk
            const size_t goff = (size_t)(m0 + r) * KDIM + kb + kq * 4;
            const float4 a = *(const float4*)(roi + goff);
            const float4 f = *(const float4*)(frm + goff);
            const float4 c = *(const float4*)(ctx + goff);
            const float4 d = make_float4(f.x - c.x, f.y - c.y, f.z - c.z, f.w - c.w);
            const int c4 = (((r >> 2) ^ kq) << 2) + (r & 3);
            s_roi[(kq * 4 + 0) * 64 + c4] = a.x;
            s_roi[(kq * 4 + 1) * 64 + c4] = a.y;
            s_roi[(kq * 4 + 2) * 64 + c4] = a.z;
            s_roi[(kq * 4 + 3) * 64 + c4] = a.w;
            s_dif[(kq * 4 + 0) * 64 + c4] = d.x;
            s_dif[(kq * 4 + 1) * 64 + c4] = d.y;
            s_dif[(kq * 4 + 2) * 64 + c4] = d.z;
            s_dif[(kq * 4 + 3) * 64 + c4] = d.w;
        }
        // ---- stage weights ----
#pragma unroll
        for (int s = 0; s < 8; ++s) {
            const int flat = tid + s * 256;       // 0..2047
            const int kl = flat >> 6, j = flat & 63;
            const int kk = kb + kl;
            float w;
            if      (j < 20) w = Wc[kk * 20 + j];
            else if (j < 41) w = W1[kk * 21 + (j - 20)];
            else if (j < 62) w = W2[kk * 21 + (j - 41)];
            else             w = 0.f;
            s_w[kl * 64 + j] = w;
        }
#pragma unroll
        for (int s = 0; s < 4; ++s) {
            const int flat = tid + s * 256;       // 0..1023
            const int kl = flat >> 5, j = flat & 31;
            s_wd[flat] = (j < 20) ? Wd[(kb + kl) * 20 + j] : 0.f;
        }
        __syncthreads();

        // ---- compute ----
#pragma unroll
        for (int k = 0; k < KB; ++k) {
            const int sw = ((ty ^ (k >> 2)) << 2);
            const float4 a  = *(const float4*)&s_roi[k * 64 + sw];
            const float4 w  = *(const float4*)&s_w  [k * 64 + (tx << 2)];
            acc[0][0] += a.x * w.x; acc[0][1] += a.x * w.y; acc[0][2] += a.x * w.z; acc[0][3] += a.x * w.w;
            acc[1][0] += a.y * w.x; acc[1][1] += a.y * w.y; acc[1][2] += a.y * w.z; acc[1][3] += a.y * w.w;
            acc[2][0] += a.z * w.x; acc[2][1] += a.z * w.y; acc[2][2] += a.z * w.z; acc[2][3] += a.z * w.w;
            acc[3][0] += a.w * w.x; acc[3][1] += a.w * w.y; acc[3][2] += a.w * w.z; acc[3][3] += a.w * w.w;
            const float4 d  = *(const float4*)&s_dif[k * 64 + sw];
            const float2 wd = *(const float2*)&s_wd[k * 32 + (tx << 1)];
            accd[0][0] += d.x * wd.x; accd[0][1] += d.x * wd.y;
            accd[1][0] += d.y * wd.x; accd[1][1] += d.y * wd.y;
            accd[2][0] += d.z * wd.x; accd[2][1] += d.z * wd.y;
            accd[3][0] += d.w * wd.x; accd[3][1] += d.w * wd.y;
        }
        __syncthreads();
    }

    const int ks = blockIdx.y;
#pragma unroll
    for (int i = 0; i < 4; ++i) {
        const int r = m0 + ty * 4 + i;
        *(float4*)&g_part[ks][r][tx * 4] =
            make_float4(acc[i][0], acc[i][1], acc[i][2], acc[i][3]);
        if (tx < 10)
            *(float2*)&g_part[ks][r][64 + tx * 2] = make_float2(accd[i][0], accd[i][1]);
    }
}

// =====================================================================
// K2: per-row epilogue (warp per row). Sums split-K partials, adds biases,
// row softmaxes for cls / r1 / r2, stores det_score raw.
// =====================================================================
__device__ __forceinline__ float warp_max(float v) {
#pragma unroll
    for (int o = 16; o; o >>= 1) v = fmaxf(v, __shfl_xor_sync(0xffffffffu, v, o));
    return v;
}
__device__ __forceinline__ float warp_sum(float v) {
#pragma unroll
    for (int o = 16; o; o >>= 1) v += __shfl_xor_sync(0xffffffffu, v, o);
    return v;
}
__device__ __forceinline__ float sum_part(int i, int c) {
    float x = g_part[0][i][c];
    x += g_part[1][i][c];
    x += g_part[2][i][c];
    x += g_part[3][i][c];
    return x;
}

__global__ void __launch_bounds__(256)
k2_row(const float* __restrict__ bc, const float* __restrict__ b1,
       const float* __restrict__ b2)
{
    const int l = threadIdx.x & 31;
    const int i = blockIdx.x * 8 + (threadIdx.x >> 5);

    // cls: cols 0..19
    {
        float x = -INFINITY;
        if (l < 20) x = sum_part(i, l) + bc[l];
        const float m = warp_max(x);
        const float e = (l < 20) ? expf(x - m) : 0.f;
        const float s = warp_sum(e);
        if (l < 20) { g_cls_score[i][l] = x; g_cls_prob[i][l] = e / s; }
    }
    // r1: cols 20..40
    {
        float x = -INFINITY;
        if (l < 21) x = sum_part(i, 20 + l) + b1[l];
        const float m = warp_max(x);
        const float e = (l < 21) ? expf(x - m) : 0.f;
        const float s = warp_sum(e);
        if (l < 21) g_prob1[i][l] = e / s;
    }
    // r2: cols 41..61
    {
        float x = -INFINITY;
        if (l < 21) x = sum_part(i, 41 + l) + b2[l];
        const float m = warp_max(x);
        const float e = (l < 21) ? expf(x - m) : 0.f;
        const float s = warp_sum(e);
        if (l < 21) g_prob2[i][l] = e / s;
    }
    // det: cols 64..83
    if (l < 20) g_det[i][l] = sum_part(i, 64 + l);
}

// =====================================================================
// K3: per-class column ops (block per class). Column softmax stats for
// det_prob, det_cls_score, and the two per-column argmaxes (first-index
// tie-break, matching jnp.argmax). Fetches the query boxes.
// =====================================================================
__global__ void __launch_bounds__(256)
k3_col(const float* __restrict__ ssb, const float* __restrict__ isw)
{
    const int c = blockIdx.x, tid = threadIdx.x;
    __shared__ float sv[256];
    __shared__ int   si[256];
    __shared__ float s_m;

    // phase 1: column max of det_score
    float m = -INFINITY;
    for (int i = tid; i < NROW; i += 256) m = fmaxf(m, g_det[i][c]);
    sv[tid] = m; __syncthreads();
    for (int s = 128; s > 0; s >>= 1) {
        if (tid < s) sv[tid] = fmaxf(sv[tid], sv[tid + s]);
        __syncthreads();
    }
    if (tid == 0) s_m = sv[0];
    __syncthreads();
    m = s_m; __syncthreads();

    // phase 2: sum(e) and sum(cls_score * e)
    float s = 0.f, t = 0.f;
    for (int i = tid; i < NROW; i += 256) {
        const float e = expf(g_det[i][c] - m);
        s += e;
        t += g_cls_score[i][c] * e;
    }
    sv[tid] = s; __syncthreads();
    for (int q = 128; q > 0; q >>= 1) { if (tid < q) sv[tid] += sv[tid + q]; __syncthreads(); }
    const float stot = sv[0]; __syncthreads();
    sv[tid] = t; __syncthreads();
    for (int q = 128; q > 0; q >>= 1) { if (tid < q) sv[tid] += sv[tid + q]; __syncthreads(); }
    if (tid == 0) g_dcs[c] = sv[0] / stot;
    __syncthreads();

    // phase 3 & 4: argmaxes (scaled by positive constant -> same argmax)
#pragma unroll
    for (int set = 0; set < 2; ++set) {
        float best = -INFINITY; int bidx = 0;
        for (int i = tid; i < NROW; i += 256) {
            const float v = (set == 0)
                ? g_cls_prob[i][c] * expf(g_det[i][c] - m) * isw[i]
                : g_prob1[i][c + 1] * isw[i];
            if (v > best) { best = v; bidx = i; }
        }
        sv[tid] = best; si[tid] = bidx; __syncthreads();
        for (int q = 128; q > 0; q >>= 1) {
            if (tid < q) {
                const float v2 = sv[tid + q]; const int i2 = si[tid + q];
                if (v2 > sv[tid] || (v2 == sv[tid] && i2 < si[tid])) { sv[tid] = v2; si[tid] = i2; }
            }
            __syncthreads();
        }
        if (tid == 0) {
            const int idx = si[0];
            g_qbox[set][c][0] = ssb[idx * 5 + 1];
            g_qbox[set][c][1] = ssb[idx * 5 + 2];
            g_qbox[set][c][2] = ssb[idx * 5 + 3];
            g_qbox[set][c][3] = ssb[idx * 5 + 4];
        }
        __syncthreads();
    }
}

// =====================================================================
// K4: IoU supervision for both refine stages + all losses, single CTA.
// =====================================================================
__global__ void __launch_bounds__(256)
k4_loss(const float* __restrict__ ssb, const float* __restrict__ isw,
        const int* __restrict__ lbl, float* __restrict__ out)
{
    __shared__ float qb[2][NCLS][4];
    __shared__ float qarea[2][NCLS];
    __shared__ int   pos[NCLS];
    __shared__ float rn1[256], rl1[256], rn2[256], rl2[256];

    const int tid = threadIdx.x;
    if (tid < NCLS) {
        pos[tid] = (lbl[tid] == 1);
#pragma unroll
        for (int s = 0; s < 2; ++s) {
            const float x1 = g_qbox[s][tid][0], y1 = g_qbox[s][tid][1];
            const float x2 = g_qbox[s][tid][2], y2 = g_qbox[s][tid][3];
            qb[s][tid][0] = x1; qb[s][tid][1] = y1; qb[s][tid][2] = x2; qb[s][tid][3] = y2;
            qarea[s][tid] = (x2 - x1 + 1.f) * (y2 - y1 + 1.f);
        }
    }
    __syncthreads();

    float n1 = 0.f, l1 = 0.f, n2 = 0.f, l2 = 0.f;
    for (int i = tid; i < NROW; i += 256) {
        const float bx1 = ssb[i * 5 + 1], by1 = ssb[i * 5 + 2];
        const float bx2 = ssb[i * 5 + 3], by2 = ssb[i * 5 + 4];
        const float ab = (bx2 - bx1 + 1.f) * (by2 - by1 + 1.f);
        const float w  = isw[i];
#pragma unroll
        for (int s = 0; s < 2; ++s) {
            float mo = -1.f; int gt = 0;
            for (int c = 0; c < NCLS; ++c) {
                if (!pos[c]) continue;   // masked cols are -1 in ref; real IoU >= 0
                const float ix1 = fmaxf(bx1, qb[s][c][0]);
                const float iy1 = fmaxf(by1, qb[s][c][1]);
                const float ix2 = fminf(bx2, qb[s][c][2]);
                const float iy2 = fminf(by2, qb[s][c][3]);
                const float iw = fmaxf(ix2 - ix1 + 1.f, 0.f);
                const float ih = fmaxf(iy2 - iy1 + 1.f, 0.f);
                const float inter = iw * ih;
                const float iou = inter / (ab + qarea[s][c] - inter);
                if (iou > mo) { mo = iou; gt = c; }
            }
            const bool fg = mo > 0.5f;
            const bool bg = (mo >= 0.1f) && (mo < 0.5f);
            if (fg || bg) {
                const int cc = fg ? gt + 1 : 0;
                const float lp = logf(s == 0 ? g_prob1[i][cc] : g_prob2[i][cc]);
                if (s == 0) { n1 += 1.f; l1 += w * lp; }
                else        { n2 += 1.f; l2 += w * lp; }
            }
        }
    }
    rn1[tid] = n1; rl1[tid] = l1; rn2[tid] = n2; rl2[tid] = l2;
    __syncthreads();
    for (int q = 128; q > 0; q >>= 1) {
        if (tid < q) {
            rn1[tid] += rn1[tid + q]; rl1[tid] += rl1[tid + q];
            rn2[tid] += rn2[tid + q]; rl2[tid] += rl2[tid + q];
        }
        __syncthreads();
    }
    if (tid == 0) {
        const float loss1 = -rl1[0] / rn1[0];
        const float loss2 = -rl2[0] / rn2[0];
        float cd = 0.f;
        for (int c = 0; c < NCLS; ++c) {
            const float labf = (float)lbl[c];
            cd += fmaxf(0.f, 1.f - labf * g_dcs[c]);
        }
        cd /= (float)NCLS;
        out[0] = cd + 0.1f * (loss1 + loss2);
    }
}

// =====================================================================
extern "C" void kernel_launch(void* const* d_in, const int* in_sizes, int n_in,
                              void* d_out, int out_size)
{
    const float* roi = (const float*)d_in[0];
    const float* ctx = (const float*)d_in[1];
    const float* frm = (const float*)d_in[2];
    const float* Wc  = (const float*)d_in[3];
    const float* bc  = (const float*)d_in[4];
    const float* Wd  = (const float*)d_in[5];
    // d_in[6] = b_det (cancels in det_score)
    const float* W1  = (const float*)d_in[7];
    const float* b1  = (const float*)d_in[8];
    const float* W2  = (const float*)d_in[9];
    const float* b2  = (const float*)d_in[10];
    const float* ssb = (const float*)d_in[11];
    const float* isw = (const float*)d_in[12];
    const int*   lbl = (const int*)d_in[13];
    float* out = (float*)d_out;

    k1_gemm<<<dim3(NROW / MT, KSPLIT), 256>>>(roi, ctx, frm, Wc, Wd, W1, W2);
    k2_row<<<NROW / 8, 256>>>(bc, b1, b2);
    k3_col<<<NCLS, 256>>>(ssb, isw);
    k4_loss<<<1, 256>>>(ssb, isw, lbl, out);
}

// round 4
// speedup vs baseline: 1.0579x; 1.0579x over previous
#include <cuda_runtime.h>
#include <math.h>

#define NROW 4096
#define KDIM 4096
#define NCLS 20
#define MT   64                   // rows per CTA in GEMM
#define KB   32                   // K-chunk staged in smem
#define KSPLIT 8
#define KCHUNK (KDIM / KSPLIT)    // 512
#define NCHUNK (KCHUNK / KB)      // 16
#define PCOLS 96                  // 0..61 roi-cols(cls|r1|r2), 64..83 det

// packed dual-fp32 FMA (exact: two independent IEEE fp32 FMAs)
#define FMA2(acc, a, b) asm("fma.rn.f32x2 %0, %1, %2, %0;" : "+l"(acc) : "l"(a), "l"(b))

// ---------------- scratch (device globals; no allocation allowed) ----------------
__device__ float g_part[KSPLIT][NROW][PCOLS];
__device__ float g_cls_score[NROW][NCLS];
__device__ float g_cls_prob [NROW][NCLS];
__device__ float g_prob1[NROW][NCLS + 1];
__device__ float g_prob2[NROW][NCLS + 1];
__device__ float g_det  [NROW][NCLS];
__device__ float g_dcs  [NCLS];
__device__ float g_qbox [2][NCLS][4];
__device__ float g_red  [64][4];

__device__ __forceinline__ float pickf(unsigned long long u, int e) {
    float2 f = *(float2*)&u;
    return e ? f.y : f.x;
}

// =====================================================================
// K1: fused split-K GEMM with packed f32x2 FMAs.
//   cols 0..19  : roi @ W_cls
//   cols 20..40 : roi @ W_r1
//   cols 41..61 : roi @ W_r2
//   cols 64..83 : (frame - ctx) @ W_det        (b_det cancels)
// A tiles transposed + XOR-swizzled in smem; element (k, r) at word
// k*64 + (((r>>2)^(k>>2))<<2) + (r&3)  -> both the scalar transpose STS and
// the 16B compute LDS are conflict-free, and 4 consecutive rows are
// contiguous, so one LDS.128 yields two packed row-pairs.
// Weights stored DUPLICATED (w,w) so one LDS yields splat pairs (no MOVs).
// =====================================================================
__global__ void __launch_bounds__(256, 3)
k1_gemm(const float* __restrict__ roi, const float* __restrict__ ctx,
        const float* __restrict__ frm,
        const float* __restrict__ Wc,  const float* __restrict__ Wd,
        const float* __restrict__ W1,  const float* __restrict__ W2)
{
    __shared__ __align__(16) float s_roi[KB * 64];
    __shared__ __align__(16) float s_dif[KB * 64];
    __shared__ __align__(16) float s_w2 [KB * 128];   // duplicated roi-side weights
    __shared__ __align__(16) float s_wd2[KB * 64];    // duplicated det weights

    const int tid = threadIdx.x;
    const int tx  = tid & 15;
    const int ty  = tid >> 4;
    const int m0  = blockIdx.x * MT;
    const int k0  = blockIdx.y * KCHUNK;

    unsigned long long accA[2][4];
    unsigned long long accD[2][2];
#pragma unroll
    for (int p = 0; p < 2; ++p) {
#pragma unroll
        for (int j = 0; j < 4; ++j) accA[p][j] = 0ull;
        accD[p][0] = 0ull; accD[p][1] = 0ull;
    }

    float4 pr_roi[2], pr_frm[2], pr_ctx[2];

    auto loadA = [&](int kb) {
#pragma unroll
        for (int s = 0; s < 2; ++s) {
            const int flat = tid + s * 256;
            const int r  = flat >> 3;
            const int kq = flat & 7;
            const size_t off = (size_t)(m0 + r) * KDIM + kb + kq * 4;
            pr_roi[s] = *(const float4*)(roi + off);
            pr_frm[s] = *(const float4*)(frm + off);
            pr_ctx[s] = *(const float4*)(ctx + off);
        }
    };
    auto storeA = [&]() {
#pragma unroll
        for (int s = 0; s < 2; ++s) {
            const int flat = tid + s * 256;
            const int r  = flat >> 3;
            const int kq = flat & 7;
            const int c4 = (((r >> 2) ^ kq) << 2) + (r & 3);
            const float4 a = pr_roi[s];
            const float4 f = pr_frm[s];
            const float4 c = pr_ctx[s];
            s_roi[(kq * 4 + 0) * 64 + c4] = a.x;
            s_roi[(kq * 4 + 1) * 64 + c4] = a.y;
            s_roi[(kq * 4 + 2) * 64 + c4] = a.z;
            s_roi[(kq * 4 + 3) * 64 + c4] = a.w;
            s_dif[(kq * 4 + 0) * 64 + c4] = f.x - c.x;
            s_dif[(kq * 4 + 1) * 64 + c4] = f.y - c.y;
            s_dif[(kq * 4 + 2) * 64 + c4] = f.z - c.z;
            s_dif[(kq * 4 + 3) * 64 + c4] = f.w - c.w;
        }
    };

    loadA(k0);

    for (int kc = 0; kc < NCHUNK; ++kc) {
        const int kb = k0 + kc * KB;
        if (kc) __syncthreads();
        storeA();
        // weights -> smem, duplicated for splat-pair loads
#pragma unroll
        for (int s = 0; s < 8; ++s) {
            const int flat = tid + s * 256;       // 0..2047
            const int kl = flat >> 6, j = flat & 63;
            const int kk = kb + kl;
            float w;
            if      (j < 20) w = Wc[kk * 20 + j];
            else if (j < 41) w = W1[kk * 21 + (j - 20)];
            else if (j < 62) w = W2[kk * 21 + (j - 41)];
            else             w = 0.f;
            *(float2*)&s_w2[kl * 128 + j * 2] = make_float2(w, w);
        }
#pragma unroll
        for (int s = 0; s < 4; ++s) {
            const int flat = tid + s * 256;       // 0..1023
            const int kl = flat >> 5, j = flat & 31;
            const float w = (j < 20) ? Wd[(kb + kl) * 20 + j] : 0.f;
            if (j < 32) *(float2*)&s_wd2[kl * 64 + j * 2] = make_float2(w, w);
        }
        __syncthreads();
        if (kc + 1 < NCHUNK) loadA(kb + KB);      // prefetch next A chunk

#pragma unroll 8
        for (int k = 0; k < KB; ++k) {
            const int sw = ((ty ^ (k >> 2)) << 2);
            const ulonglong2 a2 = *(const ulonglong2*)&s_roi[k * 64 + sw];
            const ulonglong2 d2 = *(const ulonglong2*)&s_dif[k * 64 + sw];
            const ulonglong2 wA = *(const ulonglong2*)&s_w2 [k * 128 + (tx << 3)];
            const ulonglong2 wB = *(const ulonglong2*)&s_w2 [k * 128 + (tx << 3) + 4];
            const ulonglong2 wD = *(const ulonglong2*)&s_wd2[k * 64 + (tx << 2)];
            FMA2(accA[0][0], a2.x, wA.x);
            FMA2(accA[0][1], a2.x, wA.y);
            FMA2(accA[0][2], a2.x, wB.x);
            FMA2(accA[0][3], a2.x, wB.y);
            FMA2(accA[1][0], a2.y, wA.x);
            FMA2(accA[1][1], a2.y, wA.y);
            FMA2(accA[1][2], a2.y, wB.x);
            FMA2(accA[1][3], a2.y, wB.y);
            FMA2(accD[0][0], d2.x, wD.x);
            FMA2(accD[0][1], d2.x, wD.y);
            FMA2(accD[1][0], d2.y, wD.x);
            FMA2(accD[1][1], d2.y, wD.y);
        }
    }

    const int ks = blockIdx.y;
#pragma unroll
    for (int p = 0; p < 2; ++p) {
#pragma unroll
        for (int e = 0; e < 2; ++e) {
            const int r = m0 + ty * 4 + p * 2 + e;
            *(float4*)&g_part[ks][r][tx * 4] = make_float4(
                pickf(accA[p][0], e), pickf(accA[p][1], e),
                pickf(accA[p][2], e), pickf(accA[p][3], e));
            if (tx < 10)
                *(float2*)&g_part[ks][r][64 + tx * 2] =
                    make_float2(pickf(accD[p][0], e), pickf(accD[p][1], e));
        }
    }
}

// =====================================================================
// K2: per-row epilogue (warp per row).
// =====================================================================
__device__ __forceinline__ float warp_max(float v) {
#pragma unroll
    for (int o = 16; o; o >>= 1) v = fmaxf(v, __shfl_xor_sync(0xffffffffu, v, o));
    return v;
}
__device__ __forceinline__ float warp_sum(float v) {
#pragma unroll
    for (int o = 16; o; o >>= 1) v += __shfl_xor_sync(0xffffffffu, v, o);
    return v;
}
__device__ __forceinline__ float sum_part(int i, int c) {
    float x = 0.f;
#pragma unroll
    for (int s = 0; s < KSPLIT; ++s) x += g_part[s][i][c];
    return x;
}

__global__ void __launch_bounds__(256)
k2_row(const float* __restrict__ bc, const float* __restrict__ b1,
       const float* __restrict__ b2)
{
    const int l = threadIdx.x & 31;
    const int i = blockIdx.x * 8 + (threadIdx.x >> 5);

    {   // cls
        float x = -INFINITY;
        if (l < 20) x = sum_part(i, l) + bc[l];
        const float m = warp_max(x);
        const float e = (l < 20) ? expf(x - m) : 0.f;
        const float s = warp_sum(e);
        if (l < 20) { g_cls_score[i][l] = x; g_cls_prob[i][l] = e / s; }
    }
    {   // r1
        float x = -INFINITY;
        if (l < 21) x = sum_part(i, 20 + l) + b1[l];
        const float m = warp_max(x);
        const float e = (l < 21) ? expf(x - m) : 0.f;
        const float s = warp_sum(e);
        if (l < 21) g_prob1[i][l] = e / s;
    }
    {   // r2
        float x = -INFINITY;
        if (l < 21) x = sum_part(i, 41 + l) + b2[l];
        const float m = warp_max(x);
        const float e = (l < 21) ? expf(x - m) : 0.f;
        const float s = warp_sum(e);
        if (l < 21) g_prob2[i][l] = e / s;
    }
    if (l < 20) g_det[i][l] = sum_part(i, 64 + l);
}

// =====================================================================
// K3: per-class column ops (block per class).
// =====================================================================
__global__ void __launch_bounds__(256)
k3_col(const float* __restrict__ ssb, const float* __restrict__ isw)
{
    const int c = blockIdx.x, tid = threadIdx.x;
    __shared__ float sv[256];
    __shared__ int   si[256];
    __shared__ float s_m;

    float m = -INFINITY;
    for (int i = tid; i < NROW; i += 256) m = fmaxf(m, g_det[i][c]);
    sv[tid] = m; __syncthreads();
    for (int s = 128; s > 0; s >>= 1) {
        if (tid < s) sv[tid] = fmaxf(sv[tid], sv[tid + s]);
        __syncthreads();
    }
    if (tid == 0) s_m = sv[0];
    __syncthreads();
    m = s_m; __syncthreads();

    float s = 0.f, t = 0.f;
    for (int i = tid; i < NROW; i += 256) {
        const float e = expf(g_det[i][c] - m);
        s += e;
        t += g_cls_score[i][c] * e;
    }
    sv[tid] = s; __syncthreads();
    for (int q = 128; q > 0; q >>= 1) { if (tid < q) sv[tid] += sv[tid + q]; __syncthreads(); }
    const float stot = sv[0]; __syncthreads();
    sv[tid] = t; __syncthreads();
    for (int q = 128; q > 0; q >>= 1) { if (tid < q) sv[tid] += sv[tid + q]; __syncthreads(); }
    if (tid == 0) g_dcs[c] = sv[0] / stot;
    __syncthreads();

#pragma unroll
    for (int set = 0; set < 2; ++set) {
        float best = -INFINITY; int bidx = 0;
        for (int i = tid; i < NROW; i += 256) {
            const float v = (set == 0)
                ? g_cls_prob[i][c] * expf(g_det[i][c] - m) * isw[i]
                : g_prob1[i][c + 1] * isw[i];
            if (v > best) { best = v; bidx = i; }
        }
        sv[tid] = best; si[tid] = bidx; __syncthreads();
        for (int q = 128; q > 0; q >>= 1) {
            if (tid < q) {
                const float v2 = sv[tid + q]; const int i2 = si[tid + q];
                if (v2 > sv[tid] || (v2 == sv[tid] && i2 < si[tid])) { sv[tid] = v2; si[tid] = i2; }
            }
            __syncthreads();
        }
        if (tid == 0) {
            const int idx = si[0];
            g_qbox[set][c][0] = ssb[idx * 5 + 1];
            g_qbox[set][c][1] = ssb[idx * 5 + 2];
            g_qbox[set][c][2] = ssb[idx * 5 + 3];
            g_qbox[set][c][3] = ssb[idx * 5 + 4];
        }
        __syncthreads();
    }
}

// =====================================================================
// K4a: IoU supervision + per-block partial loss sums (64 CTAs x 64 thr).
// =====================================================================
__global__ void __launch_bounds__(64)
k4a_sup(const float* __restrict__ ssb, const float* __restrict__ isw,
        const int* __restrict__ lbl)
{
    __shared__ float qb[2][NCLS][4];
    __shared__ float qarea[2][NCLS];
    __shared__ int   pos[NCLS];
    __shared__ float red[64][4];

    const int tid = threadIdx.x;
    if (tid < NCLS) {
        pos[tid] = (lbl[tid] == 1);
#pragma unroll
        for (int s = 0; s < 2; ++s) {
            const float x1 = g_qbox[s][tid][0], y1 = g_qbox[s][tid][1];
            const float x2 = g_qbox[s][tid][2], y2 = g_qbox[s][tid][3];
            qb[s][tid][0] = x1; qb[s][tid][1] = y1; qb[s][tid][2] = x2; qb[s][tid][3] = y2;
            qarea[s][tid] = (x2 - x1 + 1.f) * (y2 - y1 + 1.f);
        }
    }
    __syncthreads();

    const int i = blockIdx.x * 64 + tid;
    const float bx1 = ssb[i * 5 + 1], by1 = ssb[i * 5 + 2];
    const float bx2 = ssb[i * 5 + 3], by2 = ssb[i * 5 + 4];
    const float ab = (bx2 - bx1 + 1.f) * (by2 - by1 + 1.f);
    const float w  = isw[i];

    float n1 = 0.f, l1 = 0.f, n2 = 0.f, l2 = 0.f;
#pragma unroll
    for (int s = 0; s < 2; ++s) {
        float mo = -1.f; int gt = 0;
#pragma unroll
        for (int c = 0; c < NCLS; ++c) {
            const float ix1 = fmaxf(bx1, qb[s][c][0]);
            const float iy1 = fmaxf(by1, qb[s][c][1]);
            const float ix2 = fminf(bx2, qb[s][c][2]);
            const float iy2 = fminf(by2, qb[s][c][3]);
            const float iw = fmaxf(ix2 - ix1 + 1.f, 0.f);
            const float ih = fmaxf(iy2 - iy1 + 1.f, 0.f);
            const float inter = iw * ih;
            float iou = inter / (ab + qarea[s][c] - inter);
            iou = pos[c] ? iou : -1.f;
            if (iou > mo) { mo = iou; gt = c; }
        }
        const bool fg = mo > 0.5f;
        const bool bg = (mo >= 0.1f) && (mo < 0.5f);
        if (fg || bg) {
            const int cc = fg ? gt + 1 : 0;
            const float lp = logf(s == 0 ? g_prob1[i][cc] : g_prob2[i][cc]);
            if (s == 0) { n1 += 1.f; l1 += w * lp; }
            else        { n2 += 1.f; l2 += w * lp; }
        }
    }
    red[tid][0] = n1; red[tid][1] = l1; red[tid][2] = n2; red[tid][3] = l2;
    __syncthreads();
    for (int q = 32; q > 0; q >>= 1) {
        if (tid < q) {
#pragma unroll
            for (int j = 0; j < 4; ++j) red[tid][j] += red[tid + q][j];
        }
        __syncthreads();
    }
    if (tid == 0) {
#pragma unroll
        for (int j = 0; j < 4; ++j) g_red[blockIdx.x][j] = red[0][j];
    }
}

// =====================================================================
// K4b: final reduction + all losses (1 warp).
// =====================================================================
__global__ void __launch_bounds__(32)
k4b_loss(const int* __restrict__ lbl, float* __restrict__ out)
{
    const int l = threadIdx.x;
    float v[4];
#pragma unroll
    for (int j = 0; j < 4; ++j) {
        v[j] = g_red[l][j] + g_red[l + 32][j];
#pragma unroll
        for (int o = 16; o; o >>= 1) v[j] += __shfl_xor_sync(0xffffffffu, v[j], o);
    }
    if (l == 0) {
        const float loss1 = -v[1] / v[0];
        const float loss2 = -v[3] / v[2];
        float cd = 0.f;
        for (int c = 0; c < NCLS; ++c) {
            const float labf = (float)lbl[c];
            cd += fmaxf(0.f, 1.f - labf * g_dcs[c]);
        }
        cd /= (float)NCLS;
        out[0] = cd + 0.1f * (loss1 + loss2);
    }
}

// =====================================================================
extern "C" void kernel_launch(void* const* d_in, const int* in_sizes, int n_in,
                              void* d_out, int out_size)
{
    const float* roi = (const float*)d_in[0];
    const float* ctx = (const float*)d_in[1];
    const float* frm = (const float*)d_in[2];
    const float* Wc  = (const float*)d_in[3];
    const float* bc  = (const float*)d_in[4];
    const float* Wd  = (const float*)d_in[5];
    // d_in[6] = b_det (cancels in det_score)
    const float* W1  = (const float*)d_in[7];
    const float* b1  = (const float*)d_in[8];
    const float* W2  = (const float*)d_in[9];
    const float* b2  = (const float*)d_in[10];
    const float* ssb = (const float*)d_in[11];
    const float* isw = (const float*)d_in[12];
    const int*   lbl = (const int*)d_in[13];
    float* out = (float*)d_out;

    k1_gemm<<<dim3(NROW / MT, KSPLIT), 256>>>(roi, ctx, frm, Wc, Wd, W1, W2);
    k2_row<<<NROW / 8, 256>>>(bc, b1, b2);
    k3_col<<<NCLS, 256>>>(ssb, isw);
    k4a_sup<<<64, 64>>>(ssb, isw, lbl);
    k4b_loss<<<1, 32>>>(lbl, out);
}

// round 6
// speedup vs baseline: 2.6029x; 2.4605x over previous
#include <cuda_runtime.h>
#include <cuda_bf16.h>
#include <math.h>
#include <stdint.h>

#define NROW 4096
#define KDIM 4096
#define NCLS 20
#define KSPLIT 8
#define PCOLS 96

// ---- k1 tiling ----
#define TM   128               // rows per CTA
#define KST  32                // K per stage
#define NSTG 16                // stages: 16*32 = 512 = KDIM/KSPLIT
#define STRD 40                // padded smem row stride in bf16 (80B)

// smem byte offsets (dynamic)
#define AHI_ROI_B 0
#define ALO_ROI_B 10240
#define AHI_DIF_B 20480
#define ALO_DIF_B 30720
#define B_HI_B    40960
#define B_LO_B    48640
#define SMEM_K1   56320

// ---------------- scratch (device globals) ----------------
__device__ float g_part[KSPLIT][NROW][PCOLS];
__device__ __nv_bfloat16 g_whi[PCOLS][KDIM];
__device__ __nv_bfloat16 g_wlo[PCOLS][KDIM];
__device__ float g_prob1[NROW][NCLS + 1];
__device__ float g_prob2[NROW][NCLS + 1];
__device__ float g_detT[NCLS][NROW];
__device__ float g_clsT[NCLS][NROW];
__device__ float g_cpT [NCLS][NROW];
__device__ float g_p1wT[NCLS][NROW];
__device__ float g_dcs [NCLS];
__device__ float g_qbox[2][NCLS][4];
__device__ float g_red [32][4];

// ---------------- helpers ----------------
__device__ __forceinline__ uint32_t smem_u32(const void* p) {
    uint32_t a;
    asm("{ .reg .u64 t; cvta.to.shared.u64 t, %1; cvt.u32.u64 %0, t; }" : "=r"(a) : "l"(p));
    return a;
}

#define LDSM4(r, addr) \
    asm volatile("ldmatrix.sync.aligned.m8n8.x4.shared.b16 {%0,%1,%2,%3}, [%4];" \
        : "=r"((r)[0]), "=r"((r)[1]), "=r"((r)[2]), "=r"((r)[3]) : "r"(addr))

#define MMA(acc, a, b0, b1) \
    asm volatile("mma.sync.aligned.m16n8k16.row.col.f32.bf16.bf16.f32 " \
        "{%0,%1,%2,%3}, {%4,%5,%6,%7}, {%8,%9}, {%0,%1,%2,%3};" \
        : "+f"((acc)[0]), "+f"((acc)[1]), "+f"((acc)[2]), "+f"((acc)[3]) \
        : "r"((a)[0]), "r"((a)[1]), "r"((a)[2]), "r"((a)[3]), "r"(b0), "r"(b1))

__device__ __forceinline__ uint4 pack_hi(float4 a, float4 b) {
    union { uint4 u; __nv_bfloat162 p[4]; } r;
    r.p[0] = __floats2bfloat162_rn(a.x, a.y);
    r.p[1] = __floats2bfloat162_rn(a.z, a.w);
    r.p[2] = __floats2bfloat162_rn(b.x, b.y);
    r.p[3] = __floats2bfloat162_rn(b.z, b.w);
    return r.u;
}
__device__ __forceinline__ uint4 pack_lo(float4 a, float4 b, uint4 hu) {
    union { uint4 u; __nv_bfloat162 p[4]; } h, r;
    h.u = hu;
    r.p[0] = __floats2bfloat162_rn(a.x - __bfloat162float(h.p[0].x), a.y - __bfloat162float(h.p[0].y));
    r.p[1] = __floats2bfloat162_rn(a.z - __bfloat162float(h.p[1].x), a.w - __bfloat162float(h.p[1].y));
    r.p[2] = __floats2bfloat162_rn(b.x - __bfloat162float(h.p[2].x), b.y - __bfloat162float(h.p[2].y));
    r.p[3] = __floats2bfloat162_rn(b.z - __bfloat162float(h.p[3].x), b.w - __bfloat162float(h.p[3].y));
    return r.u;
}

// =====================================================================
// K0: weight transpose + bf16 hi/lo split (K-major rows).
// n rows: 0..19 Wc, 20..40 W1, 41..61 W2, 62..63 zero, 64..83 Wd, 84..95 zero
// =====================================================================
__global__ void __launch_bounds__(256)
k0_wt(const float* __restrict__ Wc, const float* __restrict__ Wd,
      const float* __restrict__ W1, const float* __restrict__ W2)
{
    const int n = blockIdx.x;
    const int k = blockIdx.y * 256 + threadIdx.x;
    float w = 0.f;
    if      (n < 20)            w = Wc[k * 20 + n];
    else if (n < 41)            w = W1[k * 21 + (n - 20)];
    else if (n < 62)            w = W2[k * 21 + (n - 41)];
    else if (n >= 64 && n < 84) w = Wd[k * 20 + (n - 64)];
    const __nv_bfloat16 hi = __float2bfloat16(w);
    const __nv_bfloat16 lo = __float2bfloat16(w - __bfloat162float(hi));
    g_whi[n][k] = hi;
    g_wlo[n][k] = lo;
}

// =====================================================================
// K1: warp-level bf16 mma.sync GEMM, 3-term hi/lo split.
// warps 0-3: roi rows (w*32..+32) x cols 0..63
// warps 4-7: (frm-ctx) rows ((w-4)*32..+32) x cols 64..95
// =====================================================================
template<int NP>
__device__ __forceinline__ void stage_compute(
    uint32_t sb, uint32_t aHiB, uint32_t aLoB, int nbase,
    int mrow0, int lane, float (&acc)[2][8][4])
{
    const int arow = ((lane >> 3) & 1) * 8 + (lane & 7);
    const int akof = ((lane >> 4) & 1) * 8;
    const int bn   = ((lane >> 4) & 1) * 8 + (lane & 7);
    const int bkof = ((lane >> 3) & 1) * 8;
#pragma unroll
    for (int s16 = 0; s16 < 2; ++s16) {
        uint32_t ah[2][4], al[2][4];
#pragma unroll
        for (int mt = 0; mt < 2; ++mt) {
            const uint32_t ra = (uint32_t)(((mrow0 + mt * 16 + arow) * STRD + s16 * 16 + akof) * 2);
            LDSM4(ah[mt], sb + aHiB + ra);
            LDSM4(al[mt], sb + aLoB + ra);
        }
#pragma unroll
        for (int p = 0; p < NP; ++p) {
            uint32_t bh[4], bl[4];
            const uint32_t rb = (uint32_t)(((nbase + p * 16 + bn) * STRD + s16 * 16 + bkof) * 2);
            LDSM4(bh, sb + B_HI_B + rb);
            LDSM4(bl, sb + B_LO_B + rb);
#pragma unroll
            for (int mt = 0; mt < 2; ++mt) {
                MMA(acc[mt][2 * p],     ah[mt], bh[0], bh[1]);
                MMA(acc[mt][2 * p],     ah[mt], bl[0], bl[1]);
                MMA(acc[mt][2 * p],     al[mt], bh[0], bh[1]);
                MMA(acc[mt][2 * p + 1], ah[mt], bh[2], bh[3]);
                MMA(acc[mt][2 * p + 1], ah[mt], bl[2], bl[3]);
                MMA(acc[mt][2 * p + 1], al[mt], bh[2], bh[3]);
            }
        }
    }
}

__global__ void __launch_bounds__(256)
k1_mma(const float* __restrict__ roi, const float* __restrict__ ctx,
       const float* __restrict__ frm)
{
    extern __shared__ char sm[];
    const int tid  = threadIdx.x;
    const int wid  = tid >> 5;
    const int lane = tid & 31;
    const int m0   = blockIdx.x * TM;
    const int k0   = blockIdx.y * (KST * NSTG);
    const uint32_t sb = smem_u32(sm);

    const int r = tid >> 1;        // A row 0..127
    const int h = tid & 1;         // k-half (16 each)
    const bool isRoi = (wid < 4);
    const int mrow0 = (wid & 3) * 32;

    float acc[2][8][4];
#pragma unroll
    for (int a = 0; a < 2; ++a)
#pragma unroll
        for (int b = 0; b < 8; ++b)
#pragma unroll
            for (int c = 0; c < 4; ++c) acc[a][b][c] = 0.f;

    const size_t abase = (size_t)(m0 + r) * KDIM + h * 16;
    const int nB = tid >> 1;       // B row for staging threads (tid<192)

    for (int st = 0; st < NSTG; ++st) {
        const int kb = k0 + st * KST;

        // gmem loads into regs (before sync, to get LDG in flight)
        const float4* pr = (const float4*)(roi + abase + kb);
        const float4* pf = (const float4*)(frm + abase + kb);
        const float4* pc = (const float4*)(ctx + abase + kb);
        float4 r0 = pr[0], r1 = pr[1], r2 = pr[2], r3 = pr[3];
        float4 f0 = pf[0], f1 = pf[1], f2 = pf[2], f3 = pf[3];
        float4 c0 = pc[0], c1 = pc[1], c2 = pc[2], c3 = pc[3];
        uint4 wh0, wh1, wl0, wl1;
        if (tid < 192) {
            const uint4* ph = (const uint4*)&g_whi[nB][kb + h * 16];
            const uint4* pl = (const uint4*)&g_wlo[nB][kb + h * 16];
            wh0 = ph[0]; wh1 = ph[1];
            wl0 = pl[0]; wl1 = pl[1];
        }

        __syncthreads();   // previous stage's compute done

        // stage A (roi)
        const uint32_t rowb = (uint32_t)((r * STRD + h * 16) * 2);
        {
            uint4 h0 = pack_hi(r0, r1), h1 = pack_hi(r2, r3);
            *(uint4*)(sm + AHI_ROI_B + rowb)      = h0;
            *(uint4*)(sm + AHI_ROI_B + rowb + 16) = h1;
            *(uint4*)(sm + ALO_ROI_B + rowb)      = pack_lo(r0, r1, h0);
            *(uint4*)(sm + ALO_ROI_B + rowb + 16) = pack_lo(r2, r3, h1);
        }
        // stage A (frm - ctx)
        {
            const float4 d0 = make_float4(f0.x - c0.x, f0.y - c0.y, f0.z - c0.z, f0.w - c0.w);
            const float4 d1 = make_float4(f1.x - c1.x, f1.y - c1.y, f1.z - c1.z, f1.w - c1.w);
            const float4 d2 = make_float4(f2.x - c2.x, f2.y - c2.y, f2.z - c2.z, f2.w - c2.w);
            const float4 d3 = make_float4(f3.x - c3.x, f3.y - c3.y, f3.z - c3.z, f3.w - c3.w);
            uint4 h0 = pack_hi(d0, d1), h1 = pack_hi(d2, d3);
            *(uint4*)(sm + AHI_DIF_B + rowb)      = h0;
            *(uint4*)(sm + AHI_DIF_B + rowb + 16) = h1;
            *(uint4*)(sm + ALO_DIF_B + rowb)      = pack_lo(d0, d1, h0);
            *(uint4*)(sm + ALO_DIF_B + rowb + 16) = pack_lo(d2, d3, h1);
        }
        // stage B (already bf16)
        if (tid < 192) {
            const uint32_t bb = (uint32_t)((nB * STRD + h * 16) * 2);
            *(uint4*)(sm + B_HI_B + bb)      = wh0;
            *(uint4*)(sm + B_HI_B + bb + 16) = wh1;
            *(uint4*)(sm + B_LO_B + bb)      = wl0;
            *(uint4*)(sm + B_LO_B + bb + 16) = wl1;
        }
        __syncthreads();

        if (isRoi) stage_compute<4>(sb, AHI_ROI_B, ALO_ROI_B, 0,  mrow0, lane, acc);
        else       stage_compute<2>(sb, AHI_DIF_B, ALO_DIF_B, 64, mrow0, lane, acc);
    }

    // epilogue -> split-K partials
    const int ks = blockIdx.y;
    const int ntmax = isRoi ? 8 : 4;
    const int nbc = isRoi ? 0 : 64;
#pragma unroll
    for (int mt = 0; mt < 2; ++mt) {
        for (int nt = 0; nt < ntmax; ++nt) {
            const int row = m0 + mrow0 + mt * 16 + (lane >> 2);
            const int col = nbc + nt * 8 + 2 * (lane & 3);
            *(float2*)&g_part[ks][row][col]     = make_float2(acc[mt][nt][0], acc[mt][nt][1]);
            *(float2*)&g_part[ks][row + 8][col] = make_float2(acc[mt][nt][2], acc[mt][nt][3]);
        }
    }
}

// =====================================================================
// K2: per-row epilogue (warp per row): split-K sum, biases, softmaxes,
// transposed stores for k3's coalesced column passes.
// =====================================================================
__device__ __forceinline__ float warp_max(float v) {
#pragma unroll
    for (int o = 16; o; o >>= 1) v = fmaxf(v, __shfl_xor_sync(0xffffffffu, v, o));
    return v;
}
__device__ __forceinline__ float warp_sum(float v) {
#pragma unroll
    for (int o = 16; o; o >>= 1) v += __shfl_xor_sync(0xffffffffu, v, o);
    return v;
}
__device__ __forceinline__ float sum_part(int i, int c) {
    float x = 0.f;
#pragma unroll
    for (int s = 0; s < KSPLIT; ++s) x += g_part[s][i][c];
    return x;
}

__global__ void __launch_bounds__(256)
k2_row(const float* __restrict__ bc, const float* __restrict__ b1,
       const float* __restrict__ b2, const float* __restrict__ isw)
{
    const int l = threadIdx.x & 31;
    const int i = blockIdx.x * 8 + (threadIdx.x >> 5);
    const float w = isw[i];

    {   // cls softmax (cols 0..19)
        float x = -INFINITY;
        if (l < 20) x = sum_part(i, l) + bc[l];
        const float m = warp_max(x);
        const float e = (l < 20) ? expf(x - m) : 0.f;
        const float s = warp_sum(e);
        if (l < 20) { g_clsT[l][i] = x; g_cpT[l][i] = e / s; }
    }
    {   // r1 softmax (cols 20..40)
        float x = -INFINITY;
        if (l < 21) x = sum_part(i, 20 + l) + b1[l];
        const float m = warp_max(x);
        const float e = (l < 21) ? expf(x - m) : 0.f;
        const float s = warp_sum(e);
        if (l < 21) {
            const float p = e / s;
            g_prob1[i][l] = p;
            if (l >= 1) g_p1wT[l - 1][i] = p * w;
        }
    }
    {   // r2 softmax (cols 41..61)
        float x = -INFINITY;
        if (l < 21) x = sum_part(i, 41 + l) + b2[l];
        const float m = warp_max(x);
        const float e = (l < 21) ? expf(x - m) : 0.f;
        const float s = warp_sum(e);
        if (l < 21) g_prob2[i][l] = e / s;
    }
    if (l < 20) g_detT[l][i] = sum_part(i, 64 + l);
}

// =====================================================================
// K3: per-class column ops (block per class, coalesced transposed reads).
// =====================================================================
__global__ void __launch_bounds__(256)
k3_col(const float* __restrict__ ssb, const float* __restrict__ isw)
{
    const int c = blockIdx.x, tid = threadIdx.x;
    const int wid = tid >> 5, lid = tid & 31;
    __shared__ float sred[8];
    __shared__ int   sidx[8];
    __shared__ float sbc[2];

    // pass 1: column max of det score
    float m = -INFINITY;
    for (int i = tid; i < NROW; i += 256) m = fmaxf(m, g_detT[c][i]);
    m = warp_max(m);
    if (lid == 0) sred[wid] = m;
    __syncthreads();
    if (wid == 0) {
        float t = (lid < 8) ? sred[lid] : -INFINITY;
        t = warp_max(t);
        if (lid == 0) sbc[0] = t;
    }
    __syncthreads();
    m = sbc[0];

    // pass 2: sum(e), sum(cls_score * e)
    float s = 0.f, t = 0.f;
    for (int i = tid; i < NROW; i += 256) {
        const float e = expf(g_detT[c][i] - m);
        s += e;
        t += g_clsT[c][i] * e;
    }
    s = warp_sum(s);
    if (lid == 0) sred[wid] = s;
    __syncthreads();
    if (wid == 0) {
        float x = (lid < 8) ? sred[lid] : 0.f;
        x = warp_sum(x);
        if (lid == 0) sbc[1] = x;
    }
    __syncthreads();
    const float stot = sbc[1];
    __syncthreads();
    t = warp_sum(t);
    if (lid == 0) sred[wid] = t;
    __syncthreads();
    if (wid == 0) {
        float x = (lid < 8) ? sred[lid] : 0.f;
        x = warp_sum(x);
        if (lid == 0) g_dcs[c] = x / stot;
    }
    __syncthreads();

    // passes 3&4: argmaxes (first-index tie-break)
#pragma unroll
    for (int set = 0; set < 2; ++set) {
        float best = -INFINITY;
        int bidx = 0;
        for (int i = tid; i < NROW; i += 256) {
            const float v = (set == 0)
                ? g_cpT[c][i] * expf(g_detT[c][i] - m) * isw[i]
                : g_p1wT[c][i];
            if (v > best) { best = v; bidx = i; }
        }
#pragma unroll
        for (int o = 16; o; o >>= 1) {
            const float v2 = __shfl_xor_sync(0xffffffffu, best, o);
            const int   i2 = __shfl_xor_sync(0xffffffffu, bidx, o);
            if (v2 > best || (v2 == best && i2 < bidx)) { best = v2; bidx = i2; }
        }
        if (lid == 0) { sred[wid] = best; sidx[wid] = bidx; }
        __syncthreads();
        if (tid == 0) {
            float bv = sred[0]; int bi = sidx[0];
            for (int q = 1; q < 8; ++q) {
                if (sred[q] > bv || (sred[q] == bv && sidx[q] < bi)) { bv = sred[q]; bi = sidx[q]; }
            }
            g_qbox[set][c][0] = ssb[bi * 5 + 1];
            g_qbox[set][c][1] = ssb[bi * 5 + 2];
            g_qbox[set][c][2] = ssb[bi * 5 + 3];
            g_qbox[set][c][3] = ssb[bi * 5 + 4];
        }
        __syncthreads();
    }
}

// =====================================================================
// K4a: IoU supervision + per-block partial loss sums (32 CTAs x 128 thr).
// =====================================================================
__global__ void __launch_bounds__(128)
k4a_sup(const float* __restrict__ ssb, const float* __restrict__ isw,
        const int* __restrict__ lbl)
{
    __shared__ float qb[2][NCLS][4];
    __shared__ float qarea[2][NCLS];
    __shared__ int   pos[NCLS];
    __shared__ float sred[4][4];

    const int tid = threadIdx.x;
    if (tid < NCLS) {
        pos[tid] = (lbl[tid] == 1);
#pragma unroll
        for (int s = 0; s < 2; ++s) {
            const float x1 = g_qbox[s][tid][0], y1 = g_qbox[s][tid][1];
            const float x2 = g_qbox[s][tid][2], y2 = g_qbox[s][tid][3];
            qb[s][tid][0] = x1; qb[s][tid][1] = y1; qb[s][tid][2] = x2; qb[s][tid][3] = y2;
            qarea[s][tid] = (x2 - x1 + 1.f) * (y2 - y1 + 1.f);
        }
    }
    __syncthreads();

    const int i = blockIdx.x * 128 + tid;
    const float bx1 = ssb[i * 5 + 1], by1 = ssb[i * 5 + 2];
    const float bx2 = ssb[i * 5 + 3], by2 = ssb[i * 5 + 4];
    const float ab = (bx2 - bx1 + 1.f) * (by2 - by1 + 1.f);
    const float w  = isw[i];

    float acc[4] = {0.f, 0.f, 0.f, 0.f};
#pragma unroll
    for (int s = 0; s < 2; ++s) {
        float mo = -1.f;
        int gt = 0;
#pragma unroll
        for (int c = 0; c < NCLS; ++c) {
            const float ix1 = fmaxf(bx1, qb[s][c][0]);
            const float iy1 = fmaxf(by1, qb[s][c][1]);
            const float ix2 = fminf(bx2, qb[s][c][2]);
            const float iy2 = fminf(by2, qb[s][c][3]);
            const float iw = fmaxf(ix2 - ix1 + 1.f, 0.f);
            const float ih = fmaxf(iy2 - iy1 + 1.f, 0.f);
            const float inter = iw * ih;
            float iou = inter / (ab + qarea[s][c] - inter);
            iou = pos[c] ? iou : -1.f;
            if (iou > mo) { mo = iou; gt = c; }
        }
        const bool fg = mo > 0.5f;
        const bool bg = (mo >= 0.1f) && (mo < 0.5f);
        if (fg || bg) {
            const int cc = fg ? gt + 1 : 0;
            const float lp = logf(s == 0 ? g_prob1[i][cc] : g_prob2[i][cc]);
            acc[2 * s + 0] = 1.f;
            acc[2 * s + 1] = w * lp;
        }
    }
#pragma unroll
    for (int j = 0; j < 4; ++j) acc[j] = warp_sum(acc[j]);
    if ((tid & 31) == 0) {
#pragma unroll
        for (int j = 0; j < 4; ++j) sred[tid >> 5][j] = acc[j];
    }
    __syncthreads();
    if (tid == 0) {
#pragma unroll
        for (int j = 0; j < 4; ++j)
            g_red[blockIdx.x][j] = sred[0][j] + sred[1][j] + sred[2][j] + sred[3][j];
    }
}

// =====================================================================
// K4b: final reduction + losses (1 warp).
// =====================================================================
__global__ void __launch_bounds__(32)
k4b_loss(const int* __restrict__ lbl, float* __restrict__ out)
{
    const int l = threadIdx.x;
    float v[4];
#pragma unroll
    for (int j = 0; j < 4; ++j) {
        v[j] = g_red[l][j];
#pragma unroll
        for (int o = 16; o; o >>= 1) v[j] += __shfl_xor_sync(0xffffffffu, v[j], o);
    }
    if (l == 0) {
        const float loss1 = -v[1] / v[0];
        const float loss2 = -v[3] / v[2];
        float cd = 0.f;
        for (int c = 0; c < NCLS; ++c) {
            const float labf = (float)lbl[c];
            cd += fmaxf(0.f, 1.f - labf * g_dcs[c]);
        }
        cd /= (float)NCLS;
        out[0] = cd + 0.1f * (loss1 + loss2);
    }
}

// =====================================================================
extern "C" void kernel_launch(void* const* d_in, const int* in_sizes, int n_in,
                              void* d_out, int out_size)
{
    const float* roi = (const float*)d_in[0];
    const float* ctx = (const float*)d_in[1];
    const float* frm = (const float*)d_in[2];
    const float* Wc  = (const float*)d_in[3];
    const float* bc  = (const float*)d_in[4];
    const float* Wd  = (const float*)d_in[5];
    // d_in[6] = b_det (cancels in det_score)
    const float* W1  = (const float*)d_in[7];
    const float* b1  = (const float*)d_in[8];
    const float* W2  = (const float*)d_in[9];
    const float* b2  = (const float*)d_in[10];
    const float* ssb = (const float*)d_in[11];
    const float* isw = (const float*)d_in[12];
    const int*   lbl = (const int*)d_in[13];
    float* out = (float*)d_out;

    static int smem_set = 0;
    if (!smem_set) {
        cudaFuncSetAttribute(k1_mma, cudaFuncAttributeMaxDynamicSharedMemorySize, SMEM_K1);
        smem_set = 1;
    }

    k0_wt<<<dim3(PCOLS, KDIM / 256), 256>>>(Wc, Wd, W1, W2);
    k1_mma<<<dim3(NROW / TM, KSPLIT), 256, SMEM_K1>>>(roi, ctx, frm);
    k2_row<<<NROW / 8, 256>>>(bc, b1, b2, isw);
    k3_col<<<NCLS, 256>>>(ssb, isw);
    k4a_sup<<<32, 128>>>(ssb, isw, lbl);
    k4b_loss<<<1, 32>>>(lbl, out);
}

// round 8
// speedup vs baseline: 2.8678x; 1.1018x over previous
#include <cuda_runtime.h>
#include <cuda_bf16.h>
#include <math.h>
#include <stdint.h>

#define NROW 4096
#define KDIM 4096
#define NCLS 20
#define KSPLIT 8
#define PCOLS 96

// ---- k1 tiling ----
#define TM   128               // rows per CTA
#define KST  32                // K per stage
#define NSTG 16                // stages: 16*32 = 512 = KDIM/KSPLIT
#define STRD 40                // padded smem row stride in bf16 (80B)

// smem byte offsets (dynamic)
#define AHI_ROI_B 0
#define ALO_ROI_B 10240
#define AHI_DIF_B 20480
#define ALO_DIF_B 30720
#define B_HI_B    40960
#define B_LO_B    48640
#define SMEM_K1   56320

// ---------------- scratch (device globals) ----------------
__device__ float g_part[KSPLIT][NROW][PCOLS];
__device__ __nv_bfloat16 g_whi[PCOLS][KDIM];
__device__ __nv_bfloat16 g_wlo[PCOLS][KDIM];
__device__ float g_prob1[NROW][NCLS + 1];
__device__ float g_prob2[NROW][NCLS + 1];
__device__ float g_detT[NCLS][NROW];
__device__ float g_clsT[NCLS][NROW];
__device__ float g_cpT [NCLS][NROW];
__device__ float g_p1wT[NCLS][NROW];
__device__ float g_dcs [NCLS];
__device__ float g_qbox[2][NCLS][4];
__device__ float g_red [128][4];

// ---------------- helpers ----------------
__device__ __forceinline__ uint32_t smem_u32(const void* p) {
    uint32_t a;
    asm("{ .reg .u64 t; cvta.to.shared.u64 t, %1; cvt.u32.u64 %0, t; }" : "=r"(a) : "l"(p));
    return a;
}

#define LDSM4(r, addr) \
    asm volatile("ldmatrix.sync.aligned.m8n8.x4.shared.b16 {%0,%1,%2,%3}, [%4];" \
        : "=r"((r)[0]), "=r"((r)[1]), "=r"((r)[2]), "=r"((r)[3]) : "r"(addr))

#define MMA(acc, a, b0, b1) \
    asm volatile("mma.sync.aligned.m16n8k16.row.col.f32.bf16.bf16.f32 " \
        "{%0,%1,%2,%3}, {%4,%5,%6,%7}, {%8,%9}, {%0,%1,%2,%3};" \
        : "+f"((acc)[0]), "+f"((acc)[1]), "+f"((acc)[2]), "+f"((acc)[3]) \
        : "r"((a)[0]), "r"((a)[1]), "r"((a)[2]), "r"((a)[3]), "r"(b0), "r"(b1))

__device__ __forceinline__ uint4 pack_hi(float4 a, float4 b) {
    union { uint4 u; __nv_bfloat162 p[4]; } r;
    r.p[0] = __floats2bfloat162_rn(a.x, a.y);
    r.p[1] = __floats2bfloat162_rn(a.z, a.w);
    r.p[2] = __floats2bfloat162_rn(b.x, b.y);
    r.p[3] = __floats2bfloat162_rn(b.z, b.w);
    return r.u;
}
__device__ __forceinline__ uint4 pack_lo(float4 a, float4 b, uint4 hu) {
    union { uint4 u; __nv_bfloat162 p[4]; } h, r;
    h.u = hu;
    r.p[0] = __floats2bfloat162_rn(a.x - __bfloat162float(h.p[0].x), a.y - __bfloat162float(h.p[0].y));
    r.p[1] = __floats2bfloat162_rn(a.z - __bfloat162float(h.p[1].x), a.w - __bfloat162float(h.p[1].y));
    r.p[2] = __floats2bfloat162_rn(b.x - __bfloat162float(h.p[2].x), b.y - __bfloat162float(h.p[2].y));
    r.p[3] = __floats2bfloat162_rn(b.z - __bfloat162float(h.p[3].x), b.w - __bfloat162float(h.p[3].y));
    return r.u;
}
__device__ __forceinline__ float warp_max(float v) {
#pragma unroll
    for (int o = 16; o; o >>= 1) v = fmaxf(v, __shfl_xor_sync(0xffffffffu, v, o));
    return v;
}
__device__ __forceinline__ float warp_sum(float v) {
#pragma unroll
    for (int o = 16; o; o >>= 1) v += __shfl_xor_sync(0xffffffffu, v, o);
    return v;
}

// =====================================================================
// K0: weight transpose + bf16 hi/lo split (K-major rows).
// =====================================================================
__global__ void __launch_bounds__(256)
k0_wt(const float* __restrict__ Wc, const float* __restrict__ Wd,
      const float* __restrict__ W1, const float* __restrict__ W2)
{
    const int n = blockIdx.x;
    const int k = blockIdx.y * 256 + threadIdx.x;
    float w = 0.f;
    if      (n < 20)            w = Wc[k * 20 + n];
    else if (n < 41)            w = W1[k * 21 + (n - 20)];
    else if (n < 62)            w = W2[k * 21 + (n - 41)];
    else if (n >= 64 && n < 84) w = Wd[k * 20 + (n - 64)];
    const __nv_bfloat16 hi = __float2bfloat16(w);
    const __nv_bfloat16 lo = __float2bfloat16(w - __bfloat162float(hi));
    g_whi[n][k] = hi;
    g_wlo[n][k] = lo;
}

// =====================================================================
// K1: warp-level bf16 mma.sync GEMM, 3-term hi/lo split. (unchanged R6 WIN)
// =====================================================================
template<int NP>
__device__ __forceinline__ void stage_compute(
    uint32_t sb, uint32_t aHiB, uint32_t aLoB, int nbase,
    int mrow0, int lane, float (&acc)[2][8][4])
{
    const int arow = ((lane >> 3) & 1) * 8 + (lane & 7);
    const int akof = ((lane >> 4) & 1) * 8;
    const int bn   = ((lane >> 4) & 1) * 8 + (lane & 7);
    const int bkof = ((lane >> 3) & 1) * 8;
#pragma unroll
    for (int s16 = 0; s16 < 2; ++s16) {
        uint32_t ah[2][4], al[2][4];
#pragma unroll
        for (int mt = 0; mt < 2; ++mt) {
            const uint32_t ra = (uint32_t)(((mrow0 + mt * 16 + arow) * STRD + s16 * 16 + akof) * 2);
            LDSM4(ah[mt], sb + aHiB + ra);
            LDSM4(al[mt], sb + aLoB + ra);
        }
#pragma unroll
        for (int p = 0; p < NP; ++p) {
            uint32_t bh[4], bl[4];
            const uint32_t rb = (uint32_t)(((nbase + p * 16 + bn) * STRD + s16 * 16 + bkof) * 2);
            LDSM4(bh, sb + B_HI_B + rb);
            LDSM4(bl, sb + B_LO_B + rb);
#pragma unroll
            for (int mt = 0; mt < 2; ++mt) {
                MMA(acc[mt][2 * p],     ah[mt], bh[0], bh[1]);
                MMA(acc[mt][2 * p],     ah[mt], bl[0], bl[1]);
                MMA(acc[mt][2 * p],     al[mt], bh[0], bh[1]);
                MMA(acc[mt][2 * p + 1], ah[mt], bh[2], bh[3]);
                MMA(acc[mt][2 * p + 1], ah[mt], bl[2], bl[3]);
                MMA(acc[mt][2 * p + 1], al[mt], bh[2], bh[3]);
            }
        }
    }
}

__global__ void __launch_bounds__(256)
k1_mma(const float* __restrict__ roi, const float* __restrict__ ctx,
       const float* __restrict__ frm)
{
    extern __shared__ char sm[];
    const int tid  = threadIdx.x;
    const int wid  = tid >> 5;
    const int lane = tid & 31;
    const int m0   = blockIdx.x * TM;
    const int k0   = blockIdx.y * (KST * NSTG);
    const uint32_t sb = smem_u32(sm);

    const int r = tid >> 1;
    const int h = tid & 1;
    const bool isRoi = (wid < 4);
    const int mrow0 = (wid & 3) * 32;

    float acc[2][8][4];
#pragma unroll
    for (int a = 0; a < 2; ++a)
#pragma unroll
        for (int b = 0; b < 8; ++b)
#pragma unroll
            for (int c = 0; c < 4; ++c) acc[a][b][c] = 0.f;

    const size_t abase = (size_t)(m0 + r) * KDIM + h * 16;
    const int nB = tid >> 1;

    for (int st = 0; st < NSTG; ++st) {
        const int kb = k0 + st * KST;

        const float4* pr = (const float4*)(roi + abase + kb);
        const float4* pf = (const float4*)(frm + abase + kb);
        const float4* pc = (const float4*)(ctx + abase + kb);
        float4 r0 = pr[0], r1 = pr[1], r2 = pr[2], r3 = pr[3];
        float4 f0 = pf[0], f1 = pf[1], f2 = pf[2], f3 = pf[3];
        float4 c0 = pc[0], c1 = pc[1], c2 = pc[2], c3 = pc[3];
        uint4 wh0, wh1, wl0, wl1;
        if (tid < 192) {
            const uint4* ph = (const uint4*)&g_whi[nB][kb + h * 16];
            const uint4* pl = (const uint4*)&g_wlo[nB][kb + h * 16];
            wh0 = ph[0]; wh1 = ph[1];
            wl0 = pl[0]; wl1 = pl[1];
        }

        __syncthreads();

        const uint32_t rowb = (uint32_t)((r * STRD + h * 16) * 2);
        {
            uint4 h0 = pack_hi(r0, r1), h1 = pack_hi(r2, r3);
            *(uint4*)(sm + AHI_ROI_B + rowb)      = h0;
            *(uint4*)(sm + AHI_ROI_B + rowb + 16) = h1;
            *(uint4*)(sm + ALO_ROI_B + rowb)      = pack_lo(r0, r1, h0);
            *(uint4*)(sm + ALO_ROI_B + rowb + 16) = pack_lo(r2, r3, h1);
        }
        {
            const float4 d0 = make_float4(f0.x - c0.x, f0.y - c0.y, f0.z - c0.z, f0.w - c0.w);
            const float4 d1 = make_float4(f1.x - c1.x, f1.y - c1.y, f1.z - c1.z, f1.w - c1.w);
            const float4 d2 = make_float4(f2.x - c2.x, f2.y - c2.y, f2.z - c2.z, f2.w - c2.w);
            const float4 d3 = make_float4(f3.x - c3.x, f3.y - c3.y, f3.z - c3.z, f3.w - c3.w);
            uint4 h0 = pack_hi(d0, d1), h1 = pack_hi(d2, d3);
            *(uint4*)(sm + AHI_DIF_B + rowb)      = h0;
            *(uint4*)(sm + AHI_DIF_B + rowb + 16) = h1;
            *(uint4*)(sm + ALO_DIF_B + rowb)      = pack_lo(d0, d1, h0);
            *(uint4*)(sm + ALO_DIF_B + rowb + 16) = pack_lo(d2, d3, h1);
        }
        if (tid < 192) {
            const uint32_t bb = (uint32_t)((nB * STRD + h * 16) * 2);
            *(uint4*)(sm + B_HI_B + bb)      = wh0;
            *(uint4*)(sm + B_HI_B + bb + 16) = wh1;
            *(uint4*)(sm + B_LO_B + bb)      = wl0;
            *(uint4*)(sm + B_LO_B + bb + 16) = wl1;
        }
        __syncthreads();

        if (isRoi) stage_compute<4>(sb, AHI_ROI_B, ALO_ROI_B, 0,  mrow0, lane, acc);
        else       stage_compute<2>(sb, AHI_DIF_B, ALO_DIF_B, 64, mrow0, lane, acc);
    }

    const int ks = blockIdx.y;
    const int ntmax = isRoi ? 8 : 4;
    const int nbc = isRoi ? 0 : 64;
#pragma unroll
    for (int mt = 0; mt < 2; ++mt) {
        for (int nt = 0; nt < ntmax; ++nt) {
            const int row = m0 + mrow0 + mt * 16 + (lane >> 2);
            const int col = nbc + nt * 8 + 2 * (lane & 3);
            *(float2*)&g_part[ks][row][col]     = make_float2(acc[mt][nt][0], acc[mt][nt][1]);
            *(float2*)&g_part[ks][row + 8][col] = make_float2(acc[mt][nt][2], acc[mt][nt][3]);
        }
    }
}

// =====================================================================
// K2: per-row epilogue (warp per row). Transposed stores for k3.
// =====================================================================
__device__ __forceinline__ float sum_part(int i, int c) {
    float x = 0.f;
#pragma unroll
    for (int s = 0; s < KSPLIT; ++s) x += g_part[s][i][c];
    return x;
}

__global__ void __launch_bounds__(256)
k2_row(const float* __restrict__ bc, const float* __restrict__ b1,
       const float* __restrict__ b2, const float* __restrict__ isw)
{
    const int l = threadIdx.x & 31;
    const int i = blockIdx.x * 8 + (threadIdx.x >> 5);
    const float w = isw[i];

    {   // cls softmax (cols 0..19)
        float x = -INFINITY;
        if (l < 20) x = sum_part(i, l) + bc[l];
        const float m = warp_max(x);
        const float e = (l < 20) ? expf(x - m) : 0.f;
        const float s = warp_sum(e);
        if (l < 20) { g_clsT[l][i] = x; g_cpT[l][i] = e / s; }
    }
    {   // r1 softmax (cols 20..40)
        float x = -INFINITY;
        if (l < 21) x = sum_part(i, 20 + l) + b1[l];
        const float m = warp_max(x);
        const float e = (l < 21) ? expf(x - m) : 0.f;
        const float s = warp_sum(e);
        if (l < 21) {
            const float p = e / s;
            g_prob1[i][l] = p;
            if (l >= 1) g_p1wT[l - 1][i] = p * w;
        }
    }
    {   // r2 softmax (cols 41..61)
        float x = -INFINITY;
        if (l < 21) x = sum_part(i, 41 + l) + b2[l];
        const float m = warp_max(x);
        const float e = (l < 21) ? expf(x - m) : 0.f;
        const float s = warp_sum(e);
        if (l < 21) g_prob2[i][l] = e / s;
    }
    if (l < 20) g_detT[l][i] = sum_part(i, 64 + l);
}

// =====================================================================
// K3: per-class column ops — register-resident single-load version.
// One 1024-thread block per class; each thread owns 4 contiguous rows.
// =====================================================================
__global__ void __launch_bounds__(1024)
k3_col(const float* __restrict__ ssb, const float* __restrict__ isw)
{
    const int c = blockIdx.x, tid = threadIdx.x;
    const int wid = tid >> 5, lid = tid & 31;
    __shared__ float sv[32];
    __shared__ float sv2[32];
    __shared__ int   si[32];
    __shared__ float bcast[2];

    const int i0 = tid * 4;
    const float4 det = *(const float4*)&g_detT[c][i0];
    const float4 cls = *(const float4*)&g_clsT[c][i0];
    const float4 cp  = *(const float4*)&g_cpT [c][i0];
    const float4 p1w = *(const float4*)&g_p1wT[c][i0];
    const float4 wiv = *(const float4*)&isw[i0];

    // pass 1: column max of det
    float m = fmaxf(fmaxf(det.x, det.y), fmaxf(det.z, det.w));
    m = warp_max(m);
    if (lid == 0) sv[wid] = m;
    __syncthreads();
    if (wid == 0) {
        float t = warp_max(sv[lid]);
        if (lid == 0) bcast[0] = t;
    }
    __syncthreads();
    m = bcast[0];

    // pass 2: sum(e), sum(cls * e)   (registers only)
    const float e0 = expf(det.x - m), e1 = expf(det.y - m);
    const float e2 = expf(det.z - m), e3 = expf(det.w - m);
    float s = (e0 + e1) + (e2 + e3);
    float t = (cls.x * e0 + cls.y * e1) + (cls.z * e2 + cls.w * e3);
    s = warp_sum(s);
    t = warp_sum(t);
    if (lid == 0) { sv[wid] = s; sv2[wid] = t; }
    __syncthreads();
    if (wid == 0) {
        const float a = warp_sum(sv[lid]);
        const float b = warp_sum(sv2[lid]);
        if (lid == 0) g_dcs[c] = b / a;
    }
    __syncthreads();

    // passes 3 & 4: argmaxes (strict >, first-index tie-break; order-independent)
#pragma unroll
    for (int set = 0; set < 2; ++set) {
        float v0, v1, v2, v3;
        if (set == 0) {
            v0 = cp.x * e0 * wiv.x; v1 = cp.y * e1 * wiv.y;
            v2 = cp.z * e2 * wiv.z; v3 = cp.w * e3 * wiv.w;
        } else {
            v0 = p1w.x; v1 = p1w.y; v2 = p1w.z; v3 = p1w.w;
        }
        float best = v0; int bi = i0;
        if (v1 > best) { best = v1; bi = i0 + 1; }
        if (v2 > best) { best = v2; bi = i0 + 2; }
        if (v3 > best) { best = v3; bi = i0 + 3; }
#pragma unroll
        for (int o = 16; o; o >>= 1) {
            const float vv = __shfl_xor_sync(0xffffffffu, best, o);
            const int   ii = __shfl_xor_sync(0xffffffffu, bi, o);
            if (vv > best || (vv == best && ii < bi)) { best = vv; bi = ii; }
        }
        if (lid == 0) { sv[wid] = best; si[wid] = bi; }
        __syncthreads();
        if (wid == 0) {
            float bb = sv[lid]; int ib = si[lid];
#pragma unroll
            for (int o = 16; o; o >>= 1) {
                const float vv = __shfl_xor_sync(0xffffffffu, bb, o);
                const int   ii = __shfl_xor_sync(0xffffffffu, ib, o);
                if (vv > bb || (vv == bb && ii < ib)) { bb = vv; ib = ii; }
            }
            if (lid == 0) {
                g_qbox[set][c][0] = ssb[ib * 5 + 1];
                g_qbox[set][c][1] = ssb[ib * 5 + 2];
                g_qbox[set][c][2] = ssb[ib * 5 + 3];
                g_qbox[set][c][3] = ssb[ib * 5 + 4];
            }
        }
        __syncthreads();
    }
}

// =====================================================================
// K4a: IoU supervision, thread = (row, set). 128 CTAs x 64 threads.
// =====================================================================
__global__ void __launch_bounds__(64)
k4a_sup(const float* __restrict__ ssb, const float* __restrict__ isw,
        const int* __restrict__ lbl)
{
    __shared__ float qb[2][NCLS][4];
    __shared__ float qarea[2][NCLS];
    __shared__ int   pos[NCLS];
    __shared__ float sred[2][2][2];   // [warp][set][n,l]

    const int tid = threadIdx.x;
    if (tid < NCLS * 2) {
        const int s = tid & 1, c = tid >> 1;
        if (s == 0) pos[c] = (lbl[c] == 1);
        const float x1 = g_qbox[s][c][0], y1 = g_qbox[s][c][1];
        const float x2 = g_qbox[s][c][2], y2 = g_qbox[s][c][3];
        qb[s][c][0] = x1; qb[s][c][1] = y1; qb[s][c][2] = x2; qb[s][c][3] = y2;
        qarea[s][c] = (x2 - x1 + 1.f) * (y2 - y1 + 1.f);
    }
    __syncthreads();

    const int set = tid & 1;
    const int i = blockIdx.x * 32 + (tid >> 1);
    const float bx1 = ssb[i * 5 + 1], by1 = ssb[i * 5 + 2];
    const float bx2 = ssb[i * 5 + 3], by2 = ssb[i * 5 + 4];
    const float ab = (bx2 - bx1 + 1.f) * (by2 - by1 + 1.f);
    const float w  = isw[i];

    float mo = -1.f;
    int gt = 0;
#pragma unroll
    for (int c = 0; c < NCLS; ++c) {
        const float ix1 = fmaxf(bx1, qb[set][c][0]);
        const float iy1 = fmaxf(by1, qb[set][c][1]);
        const float ix2 = fminf(bx2, qb[set][c][2]);
        const float iy2 = fminf(by2, qb[set][c][3]);
        const float iw = fmaxf(ix2 - ix1 + 1.f, 0.f);
        const float ih = fmaxf(iy2 - iy1 + 1.f, 0.f);
        const float inter = iw * ih;
        float iou = inter / (ab + qarea[set][c] - inter);
        iou = pos[c] ? iou : -1.f;
        if (iou > mo) { mo = iou; gt = c; }
    }
    float n = 0.f, l = 0.f;
    const bool fg = mo > 0.5f;
    const bool bg = (mo >= 0.1f) && (mo < 0.5f);
    if (fg || bg) {
        const int cc = fg ? gt + 1 : 0;
        n = 1.f;
        l = w * logf(set == 0 ? g_prob1[i][cc] : g_prob2[i][cc]);
    }
    // sum over same-parity lanes (sets live in even/odd lanes)
#pragma unroll
    for (int o = 2; o <= 16; o <<= 1) {
        n += __shfl_xor_sync(0xffffffffu, n, o);
        l += __shfl_xor_sync(0xffffffffu, l, o);
    }
    if ((tid & 31) < 2) {
        sred[tid >> 5][tid & 1][0] = n;
        sred[tid >> 5][tid & 1][1] = l;
    }
    __syncthreads();
    if (tid == 0) {
        g_red[blockIdx.x][0] = sred[0][0][0] + sred[1][0][0];
        g_red[blockIdx.x][1] = sred[0][0][1] + sred[1][0][1];
        g_red[blockIdx.x][2] = sred[0][1][0] + sred[1][1][0];
        g_red[blockIdx.x][3] = sred[0][1][1] + sred[1][1][1];
    }
}

// =====================================================================
// K4b: final reduction + losses (1 warp, 128 partials).
// =====================================================================
__global__ void __launch_bounds__(32)
k4b_loss(const int* __restrict__ lbl, float* __restrict__ out)
{
    const int l = threadIdx.x;
    float v[4];
#pragma unroll
    for (int j = 0; j < 4; ++j) {
        v[j] = (g_red[l][j] + g_red[l + 32][j]) + (g_red[l + 64][j] + g_red[l + 96][j]);
#pragma unroll
        for (int o = 16; o; o >>= 1) v[j] += __shfl_xor_sync(0xffffffffu, v[j], o);
    }
    if (l == 0) {
        const float loss1 = -v[1] / v[0];
        const float loss2 = -v[3] / v[2];
        float cd = 0.f;
        for (int c = 0; c < NCLS; ++c) {
            const float labf = (float)lbl[c];
            cd += fmaxf(0.f, 1.f - labf * g_dcs[c]);
        }
        cd /= (float)NCLS;
        out[0] = cd + 0.1f * (loss1 + loss2);
    }
}

// =====================================================================
extern "C" void kernel_launch(void* const* d_in, const int* in_sizes, int n_in,
                              void* d_out, int out_size)
{
    const float* roi = (const float*)d_in[0];
    const float* ctx = (const float*)d_in[1];
    const float* frm = (const float*)d_in[2];
    const float* Wc  = (const float*)d_in[3];
    const float* bc  = (const float*)d_in[4];
    const float* Wd  = (const float*)d_in[5];
    // d_in[6] = b_det (cancels in det_score)
    const float* W1  = (const float*)d_in[7];
    const float* b1  = (const float*)d_in[8];
    const float* W2  = (const float*)d_in[9];
    const float* b2  = (const float*)d_in[10];
    const float* ssb = (const float*)d_in[11];
    const float* isw = (const float*)d_in[12];
    const int*   lbl = (const int*)d_in[13];
    float* out = (float*)d_out;

    static int smem_set = 0;
    if (!smem_set) {
        cudaFuncSetAttribute(k1_mma, cudaFuncAttributeMaxDynamicSharedMemorySize, SMEM_K1);
        smem_set = 1;
    }

    k0_wt<<<dim3(PCOLS, KDIM / 256), 256>>>(Wc, Wd, W1, W2);
    k1_mma<<<dim3(NROW / TM, KSPLIT), 256, SMEM_K1>>>(roi, ctx, frm);
    k2_row<<<NROW / 8, 256>>>(bc, b1, b2, isw);
    k3_col<<<NCLS, 1024>>>(ssb, isw);
    k4a_sup<<<128, 64>>>(ssb, isw, lbl);
    k4b_loss<<<1, 32>>>(lbl, out);
}

// round 9
// speedup vs baseline: 4.0213x; 1.4022x over previous
#include <cuda_runtime.h>
#include <cuda_bf16.h>
#include <math.h>
#include <stdint.h>

#define NROW 4096
#define KDIM 4096
#define NCLS 20
#define KSPLIT 4
#define PCOLS 96

// ---- k1 tiling ----
#define TM   128               // rows per CTA
#define KST  32                // K per stage
#define NSTG 32                // stages: 32*32 = 1024 = KDIM/KSPLIT
#define STRD 40                // padded smem row stride in bf16 (80B)

// smem byte offsets within one buffer
#define AHI_ROI_B 0
#define ALO_ROI_B 10240
#define AHI_DIF_B 20480
#define ALO_DIF_B 30720
#define B_HI_B    40960
#define B_LO_B    48640
#define BUFSZ     56320
#define SMEM_K1   (2 * BUFSZ)   // 112640 bytes, double buffered

// ---------------- scratch (device globals) ----------------
__device__ float g_part[KSPLIT][NROW][PCOLS];
__device__ __nv_bfloat16 g_whi[PCOLS][KDIM];
__device__ __nv_bfloat16 g_wlo[PCOLS][KDIM];
__device__ float g_prob1[NROW][NCLS + 1];
__device__ float g_prob2[NROW][NCLS + 1];
__device__ float g_detT[NCLS][NROW];
__device__ float g_clsT[NCLS][NROW];
__device__ float g_cpT [NCLS][NROW];
__device__ float g_p1wT[NCLS][NROW];
__device__ float g_dcs [NCLS];
__device__ float g_qbox[2][NCLS][4];
__device__ float g_red [128][4];

// ---------------- helpers ----------------
__device__ __forceinline__ uint32_t smem_u32(const void* p) {
    uint32_t a;
    asm("{ .reg .u64 t; cvta.to.shared.u64 t, %1; cvt.u32.u64 %0, t; }" : "=r"(a) : "l"(p));
    return a;
}

#define LDSM4(r, addr) \
    asm volatile("ldmatrix.sync.aligned.m8n8.x4.shared.b16 {%0,%1,%2,%3}, [%4];" \
        : "=r"((r)[0]), "=r"((r)[1]), "=r"((r)[2]), "=r"((r)[3]) : "r"(addr))

#define MMA(acc, a, b0, b1) \
    asm volatile("mma.sync.aligned.m16n8k16.row.col.f32.bf16.bf16.f32 " \
        "{%0,%1,%2,%3}, {%4,%5,%6,%7}, {%8,%9}, {%0,%1,%2,%3};" \
        : "+f"((acc)[0]), "+f"((acc)[1]), "+f"((acc)[2]), "+f"((acc)[3]) \
        : "r"((a)[0]), "r"((a)[1]), "r"((a)[2]), "r"((a)[3]), "r"(b0), "r"(b1))

__device__ __forceinline__ uint4 pack_hi(float4 a, float4 b) {
    union { uint4 u; __nv_bfloat162 p[4]; } r;
    r.p[0] = __floats2bfloat162_rn(a.x, a.y);
    r.p[1] = __floats2bfloat162_rn(a.z, a.w);
    r.p[2] = __floats2bfloat162_rn(b.x, b.y);
    r.p[3] = __floats2bfloat162_rn(b.z, b.w);
    return r.u;
}
__device__ __forceinline__ uint4 pack_lo(float4 a, float4 b, uint4 hu) {
    union { uint4 u; __nv_bfloat162 p[4]; } h, r;
    h.u = hu;
    r.p[0] = __floats2bfloat162_rn(a.x - __bfloat162float(h.p[0].x), a.y - __bfloat162float(h.p[0].y));
    r.p[1] = __floats2bfloat162_rn(a.z - __bfloat162float(h.p[1].x), a.w - __bfloat162float(h.p[1].y));
    r.p[2] = __floats2bfloat162_rn(b.x - __bfloat162float(h.p[2].x), b.y - __bfloat162float(h.p[2].y));
    r.p[3] = __floats2bfloat162_rn(b.z - __bfloat162float(h.p[3].x), b.w - __bfloat162float(h.p[3].y));
    return r.u;
}
__device__ __forceinline__ float warp_max(float v) {
#pragma unroll
    for (int o = 16; o; o >>= 1) v = fmaxf(v, __shfl_xor_sync(0xffffffffu, v, o));
    return v;
}
__device__ __forceinline__ float warp_sum(float v) {
#pragma unroll
    for (int o = 16; o; o >>= 1) v += __shfl_xor_sync(0xffffffffu, v, o);
    return v;
}

// =====================================================================
// K0: weight transpose + bf16 hi/lo split (K-major rows).
// =====================================================================
__global__ void __launch_bounds__(256)
k0_wt(const float* __restrict__ Wc, const float* __restrict__ Wd,
      const float* __restrict__ W1, const float* __restrict__ W2)
{
    const int n = blockIdx.x;
    const int k = blockIdx.y * 256 + threadIdx.x;
    float w = 0.f;
    if      (n < 20)            w = Wc[k * 20 + n];
    else if (n < 41)            w = W1[k * 21 + (n - 20)];
    else if (n < 62)            w = W2[k * 21 + (n - 41)];
    else if (n >= 64 && n < 84) w = Wd[k * 20 + (n - 64)];
    const __nv_bfloat16 hi = __float2bfloat16(w);
    const __nv_bfloat16 lo = __float2bfloat16(w - __bfloat162float(hi));
    g_whi[n][k] = hi;
    g_wlo[n][k] = lo;
}

// =====================================================================
// K1: warp-level bf16 mma.sync GEMM, 3-term hi/lo split.
// Double-buffered smem, single sync per stage, LDG prefetch hidden
// behind compute.
//   warps 0-3: roi rows x cols 0..63;  warps 4-7: (frm-ctx) x cols 64..95
// =====================================================================
template<int NP>
__device__ __forceinline__ void stage_compute(
    uint32_t sbuf, uint32_t aHiB, uint32_t aLoB, int nbase,
    int mrow0, int lane, float (&acc)[2][8][4])
{
    const int arow = ((lane >> 3) & 1) * 8 + (lane & 7);
    const int akof = ((lane >> 4) & 1) * 8;
    const int bn   = ((lane >> 4) & 1) * 8 + (lane & 7);
    const int bkof = ((lane >> 3) & 1) * 8;
#pragma unroll
    for (int s16 = 0; s16 < 2; ++s16) {
        uint32_t ah[2][4], al[2][4];
#pragma unroll
        for (int mt = 0; mt < 2; ++mt) {
            const uint32_t ra = (uint32_t)(((mrow0 + mt * 16 + arow) * STRD + s16 * 16 + akof) * 2);
            LDSM4(ah[mt], sbuf + aHiB + ra);
            LDSM4(al[mt], sbuf + aLoB + ra);
        }
#pragma unroll
        for (int p = 0; p < NP; ++p) {
            uint32_t bh[4], bl[4];
            const uint32_t rb = (uint32_t)(((nbase + p * 16 + bn) * STRD + s16 * 16 + bkof) * 2);
            LDSM4(bh, sbuf + B_HI_B + rb);
            LDSM4(bl, sbuf + B_LO_B + rb);
#pragma unroll
            for (int mt = 0; mt < 2; ++mt) {
                MMA(acc[mt][2 * p],     ah[mt], bh[0], bh[1]);
                MMA(acc[mt][2 * p],     ah[mt], bl[0], bl[1]);
                MMA(acc[mt][2 * p],     al[mt], bh[0], bh[1]);
                MMA(acc[mt][2 * p + 1], ah[mt], bh[2], bh[3]);
                MMA(acc[mt][2 * p + 1], ah[mt], bl[2], bl[3]);
                MMA(acc[mt][2 * p + 1], al[mt], bh[2], bh[3]);
            }
        }
    }
}

__global__ void __launch_bounds__(256)
k1_mma(const float* __restrict__ roi, const float* __restrict__ ctx,
       const float* __restrict__ frm)
{
    extern __shared__ char sm[];
    const int tid  = threadIdx.x;
    const int wid  = tid >> 5;
    const int lane = tid & 31;
    const int m0   = blockIdx.x * TM;
    const int k0   = blockIdx.y * (KST * NSTG);
    const uint32_t sb = smem_u32(sm);

    const int r = tid >> 1;
    const int h = tid & 1;
    const bool isRoi = (wid < 4);
    const int mrow0 = (wid & 3) * 32;

    float acc[2][8][4];
#pragma unroll
    for (int a = 0; a < 2; ++a)
#pragma unroll
        for (int b = 0; b < 8; ++b)
#pragma unroll
            for (int c = 0; c < 4; ++c) acc[a][b][c] = 0.f;

    const size_t abase = (size_t)(m0 + r) * KDIM + h * 16;
    const int nB = tid >> 1;

    // stage registers (live across compute in the pipelined loop)
    float4 r0, r1, r2, r3, f0, f1, f2, f3, c0, c1, c2, c3;
    uint4 wh0, wh1, wl0, wl1;

    auto LOAD = [&](int st) {
        const int kb = k0 + st * KST;
        const float4* pr = (const float4*)(roi + abase + kb);
        const float4* pf = (const float4*)(frm + abase + kb);
        const float4* pc = (const float4*)(ctx + abase + kb);
        r0 = pr[0]; r1 = pr[1]; r2 = pr[2]; r3 = pr[3];
        f0 = pf[0]; f1 = pf[1]; f2 = pf[2]; f3 = pf[3];
        c0 = pc[0]; c1 = pc[1]; c2 = pc[2]; c3 = pc[3];
        if (tid < 192) {
            const uint4* ph = (const uint4*)&g_whi[nB][kb + h * 16];
            const uint4* pl = (const uint4*)&g_wlo[nB][kb + h * 16];
            wh0 = ph[0]; wh1 = ph[1];
            wl0 = pl[0]; wl1 = pl[1];
        }
    };
    auto STORE = [&](int st) {
        char* bs = sm + (st & 1) * BUFSZ;
        const uint32_t rowb = (uint32_t)((r * STRD + h * 16) * 2);
        {
            uint4 h0 = pack_hi(r0, r1), h1 = pack_hi(r2, r3);
            *(uint4*)(bs + AHI_ROI_B + rowb)      = h0;
            *(uint4*)(bs + AHI_ROI_B + rowb + 16) = h1;
            *(uint4*)(bs + ALO_ROI_B + rowb)      = pack_lo(r0, r1, h0);
            *(uint4*)(bs + ALO_ROI_B + rowb + 16) = pack_lo(r2, r3, h1);
        }
        {
            const float4 d0 = make_float4(f0.x - c0.x, f0.y - c0.y, f0.z - c0.z, f0.w - c0.w);
            const float4 d1 = make_float4(f1.x - c1.x, f1.y - c1.y, f1.z - c1.z, f1.w - c1.w);
            const float4 d2 = make_float4(f2.x - c2.x, f2.y - c2.y, f2.z - c2.z, f2.w - c2.w);
            const float4 d3 = make_float4(f3.x - c3.x, f3.y - c3.y, f3.z - c3.z, f3.w - c3.w);
            uint4 h0 = pack_hi(d0, d1), h1 = pack_hi(d2, d3);
            *(uint4*)(bs + AHI_DIF_B + rowb)      = h0;
            *(uint4*)(bs + AHI_DIF_B + rowb + 16) = h1;
            *(uint4*)(bs + ALO_DIF_B + rowb)      = pack_lo(d0, d1, h0);
            *(uint4*)(bs + ALO_DIF_B + rowb + 16) = pack_lo(d2, d3, h1);
        }
        if (tid < 192) {
            const uint32_t bb = (uint32_t)((nB * STRD + h * 16) * 2);
            *(uint4*)(bs + B_HI_B + bb)      = wh0;
            *(uint4*)(bs + B_HI_B + bb + 16) = wh1;
            *(uint4*)(bs + B_LO_B + bb)      = wl0;
            *(uint4*)(bs + B_LO_B + bb + 16) = wl1;
        }
    };

    // prologue: fill buffer 0
    LOAD(0);
    STORE(0);

    for (int st = 0; st < NSTG; ++st) {
        if (st + 1 < NSTG) LOAD(st + 1);         // LDG in flight during sync+compute
        __syncthreads();                         // buf[st&1] fully staged
        const uint32_t sbuf = sb + (uint32_t)((st & 1) * BUFSZ);
        if (isRoi) stage_compute<4>(sbuf, AHI_ROI_B, ALO_ROI_B, 0,  mrow0, lane, acc);
        else       stage_compute<2>(sbuf, AHI_DIF_B, ALO_DIF_B, 64, mrow0, lane, acc);
        if (st + 1 < NSTG) STORE(st + 1);        // into the other buffer; next sync orders it
    }

    const int ks = blockIdx.y;
    const int ntmax = isRoi ? 8 : 4;
    const int nbc = isRoi ? 0 : 64;
#pragma unroll
    for (int mt = 0; mt < 2; ++mt) {
        for (int nt = 0; nt < ntmax; ++nt) {
            const int row = m0 + mrow0 + mt * 16 + (lane >> 2);
            const int col = nbc + nt * 8 + 2 * (lane & 3);
            *(float2*)&g_part[ks][row][col]     = make_float2(acc[mt][nt][0], acc[mt][nt][1]);
            *(float2*)&g_part[ks][row + 8][col] = make_float2(acc[mt][nt][2], acc[mt][nt][3]);
        }
    }
}

// =====================================================================
// K2: per-row epilogue (warp per row). Transposed stores for k3.
// =====================================================================
__device__ __forceinline__ float sum_part(int i, int c) {
    float x = 0.f;
#pragma unroll
    for (int s = 0; s < KSPLIT; ++s) x += g_part[s][i][c];
    return x;
}

__global__ void __launch_bounds__(256)
k2_row(const float* __restrict__ bc, const float* __restrict__ b1,
       const float* __restrict__ b2, const float* __restrict__ isw)
{
    const int l = threadIdx.x & 31;
    const int i = blockIdx.x * 8 + (threadIdx.x >> 5);
    const float w = isw[i];

    {   // cls softmax (cols 0..19)
        float x = -INFINITY;
        if (l < 20) x = sum_part(i, l) + bc[l];
        const float m = warp_max(x);
        const float e = (l < 20) ? expf(x - m) : 0.f;
        const float s = warp_sum(e);
        if (l < 20) { g_clsT[l][i] = x; g_cpT[l][i] = e / s; }
    }
    {   // r1 softmax (cols 20..40)
        float x = -INFINITY;
        if (l < 21) x = sum_part(i, 20 + l) + b1[l];
        const float m = warp_max(x);
        const float e = (l < 21) ? expf(x - m) : 0.f;
        const float s = warp_sum(e);
        if (l < 21) {
            const float p = e / s;
            g_prob1[i][l] = p;
            if (l >= 1) g_p1wT[l - 1][i] = p * w;
        }
    }
    {   // r2 softmax (cols 41..61)
        float x = -INFINITY;
        if (l < 21) x = sum_part(i, 41 + l) + b2[l];
        const float m = warp_max(x);
        const float e = (l < 21) ? expf(x - m) : 0.f;
        const float s = warp_sum(e);
        if (l < 21) g_prob2[i][l] = e / s;
    }
    if (l < 20) g_detT[l][i] = sum_part(i, 64 + l);
}

// =====================================================================
// K3: per-class column ops — register-resident single-load version.
// =====================================================================
__global__ void __launch_bounds__(1024)
k3_col(const float* __restrict__ ssb, const float* __restrict__ isw)
{
    const int c = blockIdx.x, tid = threadIdx.x;
    const int wid = tid >> 5, lid = tid & 31;
    __shared__ float sv[32];
    __shared__ float sv2[32];
    __shared__ int   si[32];
    __shared__ float bcast[2];

    const int i0 = tid * 4;
    const float4 det = *(const float4*)&g_detT[c][i0];
    const float4 cls = *(const float4*)&g_clsT[c][i0];
    const float4 cp  = *(const float4*)&g_cpT [c][i0];
    const float4 p1w = *(const float4*)&g_p1wT[c][i0];
    const float4 wiv = *(const float4*)&isw[i0];

    // pass 1: column max of det
    float m = fmaxf(fmaxf(det.x, det.y), fmaxf(det.z, det.w));
    m = warp_max(m);
    if (lid == 0) sv[wid] = m;
    __syncthreads();
    if (wid == 0) {
        float t = warp_max(sv[lid]);
        if (lid == 0) bcast[0] = t;
    }
    __syncthreads();
    m = bcast[0];

    // pass 2: sum(e), sum(cls * e)
    const float e0 = expf(det.x - m), e1 = expf(det.y - m);
    const float e2 = expf(det.z - m), e3 = expf(det.w - m);
    float s = (e0 + e1) + (e2 + e3);
    float t = (cls.x * e0 + cls.y * e1) + (cls.z * e2 + cls.w * e3);
    s = warp_sum(s);
    t = warp_sum(t);
    if (lid == 0) { sv[wid] = s; sv2[wid] = t; }
    __syncthreads();
    if (wid == 0) {
        const float a = warp_sum(sv[lid]);
        const float b = warp_sum(sv2[lid]);
        if (lid == 0) g_dcs[c] = b / a;
    }
    __syncthreads();

    // passes 3 & 4: argmaxes (first-index tie-break; order-independent)
#pragma unroll
    for (int set = 0; set < 2; ++set) {
        float v0, v1, v2, v3;
        if (set == 0) {
            v0 = cp.x * e0 * wiv.x; v1 = cp.y * e1 * wiv.y;
            v2 = cp.z * e2 * wiv.z; v3 = cp.w * e3 * wiv.w;
        } else {
            v0 = p1w.x; v1 = p1w.y; v2 = p1w.z; v3 = p1w.w;
        }
        float best = v0; int bi = i0;
        if (v1 > best) { best = v1; bi = i0 + 1; }
        if (v2 > best) { best = v2; bi = i0 + 2; }
        if (v3 > best) { best = v3; bi = i0 + 3; }
#pragma unroll
        for (int o = 16; o; o >>= 1) {
            const float vv = __shfl_xor_sync(0xffffffffu, best, o);
            const int   ii = __shfl_xor_sync(0xffffffffu, bi, o);
            if (vv > best || (vv == best && ii < bi)) { best = vv; bi = ii; }
        }
        if (lid == 0) { sv[wid] = best; si[wid] = bi; }
        __syncthreads();
        if (wid == 0) {
            float bb = sv[lid]; int ib = si[lid];
#pragma unroll
            for (int o = 16; o; o >>= 1) {
                const float vv = __shfl_xor_sync(0xffffffffu, bb, o);
                const int   ii = __shfl_xor_sync(0xffffffffu, ib, o);
                if (vv > bb || (vv == bb && ii < ib)) { bb = vv; ib = ii; }
            }
            if (lid == 0) {
                g_qbox[set][c][0] = ssb[ib * 5 + 1];
                g_qbox[set][c][1] = ssb[ib * 5 + 2];
                g_qbox[set][c][2] = ssb[ib * 5 + 3];
                g_qbox[set][c][3] = ssb[ib * 5 + 4];
            }
        }
        __syncthreads();
    }
}

// =====================================================================
// K4a: IoU supervision, thread = (row, set). 128 CTAs x 64 threads.
// =====================================================================
__global__ void __launch_bounds__(64)
k4a_sup(const float* __restrict__ ssb, const float* __restrict__ isw,
        const int* __restrict__ lbl)
{
    __shared__ float qb[2][NCLS][4];
    __shared__ float qarea[2][NCLS];
    __shared__ int   pos[NCLS];
    __shared__ float sred[2][2][2];

    const int tid = threadIdx.x;
    if (tid < NCLS * 2) {
        const int s = tid & 1, c = tid >> 1;
        if (s == 0) pos[c] = (lbl[c] == 1);
        const float x1 = g_qbox[s][c][0], y1 = g_qbox[s][c][1];
        const float x2 = g_qbox[s][c][2], y2 = g_qbox[s][c][3];
        qb[s][c][0] = x1; qb[s][c][1] = y1; qb[s][c][2] = x2; qb[s][c][3] = y2;
        qarea[s][c] = (x2 - x1 + 1.f) * (y2 - y1 + 1.f);
    }
    __syncthreads();

    const int set = tid & 1;
    const int i = blockIdx.x * 32 + (tid >> 1);
    const float bx1 = ssb[i * 5 + 1], by1 = ssb[i * 5 + 2];
    const float bx2 = ssb[i * 5 + 3], by2 = ssb[i * 5 + 4];
    const float ab = (bx2 - bx1 + 1.f) * (by2 - by1 + 1.f);
    const float w  = isw[i];

    float mo = -1.f;
    int gt = 0;
#pragma unroll
    for (int c = 0; c < NCLS; ++c) {
        const float ix1 = fmaxf(bx1, qb[set][c][0]);
        const float iy1 = fmaxf(by1, qb[set][c][1]);
        const float ix2 = fminf(bx2, qb[set][c][2]);
        const float iy2 = fminf(by2, qb[set][c][3]);
        const float iw = fmaxf(ix2 - ix1 + 1.f, 0.f);
        const float ih = fmaxf(iy2 - iy1 + 1.f, 0.f);
        const float inter = iw * ih;
        float iou = inter / (ab + qarea[set][c] - inter);
        iou = pos[c] ? iou : -1.f;
        if (iou > mo) { mo = iou; gt = c; }
    }
    float n = 0.f, l = 0.f;
    const bool fg = mo > 0.5f;
    const bool bg = (mo >= 0.1f) && (mo < 0.5f);
    if (fg || bg) {
        const int cc = fg ? gt + 1 : 0;
        n = 1.f;
        l = w * logf(set == 0 ? g_prob1[i][cc] : g_prob2[i][cc]);
    }
#pragma unroll
    for (int o = 2; o <= 16; o <<= 1) {
        n += __shfl_xor_sync(0xffffffffu, n, o);
        l += __shfl_xor_sync(0xffffffffu, l, o);
    }
    if ((tid & 31) < 2) {
        sred[tid >> 5][tid & 1][0] = n;
        sred[tid >> 5][tid & 1][1] = l;
    }
    __syncthreads();
    if (tid == 0) {
        g_red[blockIdx.x][0] = sred[0][0][0] + sred[1][0][0];
        g_red[blockIdx.x][1] = sred[0][0][1] + sred[1][0][1];
        g_red[blockIdx.x][2] = sred[0][1][0] + sred[1][1][0];
        g_red[blockIdx.x][3] = sred[0][1][1] + sred[1][1][1];
    }
}

// =====================================================================
// K4b: final reduction + losses (1 warp, 128 partials).
// =====================================================================
__global__ void __launch_bounds__(32)
k4b_loss(const int* __restrict__ lbl, float* __restrict__ out)
{
    const int l = threadIdx.x;
    float v[4];
#pragma unroll
    for (int j = 0; j < 4; ++j) {
        v[j] = (g_red[l][j] + g_red[l + 32][j]) + (g_red[l + 64][j] + g_red[l + 96][j]);
#pragma unroll
        for (int o = 16; o; o >>= 1) v[j] += __shfl_xor_sync(0xffffffffu, v[j], o);
    }
    if (l == 0) {
        const float loss1 = -v[1] / v[0];
        const float loss2 = -v[3] / v[2];
        float cd = 0.f;
        for (int c = 0; c < NCLS; ++c) {
            const float labf = (float)lbl[c];
            cd += fmaxf(0.f, 1.f - labf * g_dcs[c]);
        }
        cd /= (float)NCLS;
        out[0] = cd + 0.1f * (loss1 + loss2);
    }
}

// =====================================================================
extern "C" void kernel_launch(void* const* d_in, const int* in_sizes, int n_in,
                              void* d_out, int out_size)
{
    const float* roi = (const float*)d_in[0];
    const float* ctx = (const float*)d_in[1];
    const float* frm = (const float*)d_in[2];
    const float* Wc  = (const float*)d_in[3];
    const float* bc  = (const float*)d_in[4];
    const float* Wd  = (const float*)d_in[5];
    // d_in[6] = b_det (cancels in det_score)
    const float* W1  = (const float*)d_in[7];
    const float* b1  = (const float*)d_in[8];
    const float* W2  = (const float*)d_in[9];
    const float* b2  = (const float*)d_in[10];
    const float* ssb = (const float*)d_in[11];
    const float* isw = (const float*)d_in[12];
    const int*   lbl = (const int*)d_in[13];
    float* out = (float*)d_out;

    static int smem_set = 0;
    if (!smem_set) {
        cudaFuncSetAttribute(k1_mma, cudaFuncAttributeMaxDynamicSharedMemorySize, SMEM_K1);
        smem_set = 1;
    }

    k0_wt<<<dim3(PCOLS, KDIM / 256), 256>>>(Wc, Wd, W1, W2);
    k1_mma<<<dim3(NROW / TM, KSPLIT), 256, SMEM_K1>>>(roi, ctx, frm);
    k2_row<<<NROW / 8, 256>>>(bc, b1, b2, isw);
    k3_col<<<NCLS, 1024>>>(ssb, isw);
    k4a_sup<<<128, 64>>>(ssb, isw, lbl);
    k4b_loss<<<1, 32>>>(lbl, out);
}